// round 9
// baseline (speedup 1.0000x reference)
#include <cuda_runtime.h>
#include <cuda_bf16.h>
#include <math.h>
#include <stdint.h>

#define BSZ   8
#define LSEQ  2048
#define HDIM  512
#define NST   64
#define ROWS  (BSZ*LSEQ)      // 16384
#define SEG   16
#define SEGT  (LSEQ/SEG)      // 128

typedef __nv_bfloat16 bf16;
typedef __nv_bfloat162 bf162;

// ---------------- scratch ----------------------------------------------------------
__device__ float g_wre[HDIM*NST];
__device__ float g_wim[HDIM*NST];
__device__ float g_wTre[HDIM*NST];
__device__ float g_wTim[HDIM*NST];
__device__ float g_ctre[HDIM*NST];
__device__ float g_ctim[HDIM*NST];

__device__ float g_sendre[(size_t)BSZ*HDIM*SEG*NST];
__device__ float g_sendim[(size_t)BSZ*HDIM*SEG*NST];
__device__ float g_carre [(size_t)BSZ*HDIM*SEG*NST];
__device__ float g_carim [(size_t)BSZ*HDIM*SEG*NST];

__device__ bf16  g_yh [(size_t)ROWS*HDIM];
__device__ bf16  g_yl [(size_t)ROWS*HDIM];
__device__ float g_z  [(size_t)ROWS*2*HDIM];
__device__ float g_xln[(size_t)ROWS*HDIM];
__device__ bf16  g_xh [(size_t)ROWS*HDIM];
__device__ bf16  g_xl [(size_t)ROWS*HDIM];
__device__ bf16  g_y1h[(size_t)ROWS*HDIM];
__device__ bf16  g_y1l[(size_t)ROWS*HDIM];
__device__ float g_y2 [(size_t)ROWS*HDIM];

__device__ bf16 g_wouth[2*HDIM*HDIM];
__device__ bf16 g_woutl[2*HDIM*HDIM];
__device__ bf16 g_w1h[HDIM*HDIM];
__device__ bf16 g_w1l[HDIM*HDIM];
__device__ bf16 g_w2h[HDIM*HDIM];
__device__ bf16 g_w2l[HDIM*HDIM];

// =============================== helpers =========================================
__device__ __forceinline__ uint32_t smem_u32(const void* p) {
    uint32_t a;
    asm("{ .reg .u64 t; cvta.to.shared.u64 t, %1; cvt.u32.u64 %0, t; }" : "=r"(a) : "l"(p));
    return a;
}

__device__ __forceinline__ void ldmatrix_x4(uint32_t* r, uint32_t addr) {
    asm volatile("ldmatrix.sync.aligned.m8n8.x4.shared.b16 {%0,%1,%2,%3}, [%4];"
        : "=r"(r[0]), "=r"(r[1]), "=r"(r[2]), "=r"(r[3]) : "r"(addr));
}

__device__ __forceinline__ void mma_bf16(float* c, const uint32_t* a,
                                         uint32_t b0, uint32_t b1) {
    asm volatile("mma.sync.aligned.m16n8k16.row.col.f32.bf16.bf16.f32 "
        "{%0,%1,%2,%3}, {%4,%5,%6,%7}, {%8,%9}, {%0,%1,%2,%3};"
        : "+f"(c[0]), "+f"(c[1]), "+f"(c[2]), "+f"(c[3])
        : "r"(a[0]), "r"(a[1]), "r"(a[2]), "r"(a[3]), "r"(b0), "r"(b1));
}

#define CP_ASYNC16(saddr, gaddr) \
    asm volatile("cp.async.cg.shared.global [%0], [%1], 16;" \
                 :: "r"(saddr), "l"(gaddr) : "memory")
#define CP_COMMIT() asm volatile("cp.async.commit_group;" ::: "memory")
#define CP_WAIT(n)  asm volatile("cp.async.wait_group %0;" :: "n"(n) : "memory")

__device__ __forceinline__ void split1(float v, bf16& h, bf16& l) {
    h = __float2bfloat16(v);
    l = __float2bfloat16(v - __bfloat162float(h));
}

// ---- packed f32x2 ops (Blackwell) ----
__device__ __forceinline__ uint64_t pk2(float lo, float hi) {
    uint64_t r; asm("mov.b64 %0, {%1,%2};" : "=l"(r) : "f"(lo), "f"(hi)); return r;
}
__device__ __forceinline__ void upk2(uint64_t v, float& lo, float& hi) {
    asm("mov.b64 {%0,%1}, %2;" : "=f"(lo), "=f"(hi) : "l"(v));
}
__device__ __forceinline__ uint64_t fma2(uint64_t a, uint64_t b, uint64_t c) {
    uint64_t d; asm("fma.rn.f32x2 %0, %1, %2, %3;" : "=l"(d) : "l"(a), "l"(b), "l"(c)); return d;
}
__device__ __forceinline__ uint64_t mul2(uint64_t a, uint64_t b) {
    uint64_t d; asm("mul.rn.f32x2 %0, %1, %2;" : "=l"(d) : "l"(a), "l"(b)); return d;
}
__device__ __forceinline__ uint64_t add2(uint64_t a, uint64_t b) {
    uint64_t d; asm("add.rn.f32x2 %0, %1, %2;" : "=l"(d) : "l"(a), "l"(b)); return d;
}

// ---------------- weight split -----------------------------------------------------
__global__ void split_all_kernel(const float* __restrict__ wout,
                                 const float* __restrict__ w1,
                                 const float* __restrict__ w2) {
    int i = blockIdx.x * blockDim.x + threadIdx.x;
    const int n1 = 2 * HDIM * HDIM;
    const int n2 = HDIM * HDIM;
    if (i < n1) {
        bf16 h, l; split1(wout[i], h, l);
        g_wouth[i] = h; g_woutl[i] = l;
    } else if (i < n1 + n2) {
        int j = i - n1;
        bf16 h, l; split1(w1[j], h, l);
        g_w1h[j] = h; g_w1l[j] = l;
    } else {
        int j = i - n1 - n2;
        bf16 h, l; split1(w2[j], h, l);
        g_w2h[j] = h; g_w2l[j] = l;
    }
}

// ---------------- precompute -------------------------------------------------------
__global__ void precompute_kernel(const float* __restrict__ log_dt,
                                  const float* __restrict__ Are,
                                  const float* __restrict__ Aim,
                                  const float* __restrict__ Cre,
                                  const float* __restrict__ Cim) {
    int h = blockIdx.x, n = threadIdx.x;
    int idx = h * NST + n;
    float dt = expf(log_dt[h]);
    float ar = Are[idx] * dt;
    float ai = Aim[idx] * dt;
    float e  = expf(ar);
    float sb, cb;
    sincosf(ai, &sb, &cb);
    float wre = e * cb, wim = e * sb;
    float eT = expf(ar * (float)SEGT);
    float sT, cT;
    sincosf(ai * (float)SEGT, &sT, &cT);
    g_wTre[idx] = eT * cT;
    g_wTim[idx] = eT * sT;

    float Ere = wre - 1.0f, Eim = wim;
    float Ar = Are[idx], Ai = Aim[idx];
    float inv = 1.0f / (Ar * Ar + Ai * Ai);
    float rre = (Ere * Ar + Eim * Ai) * inv;
    float rim = (Eim * Ar - Ere * Ai) * inv;
    float cr = Cre[idx], ci = Cim[idx];
    g_ctre[idx] = cr * rre - ci * rim;
    g_ctim[idx] = cr * rim + ci * rre;
    g_wre[idx]  = wre;
    g_wim[idx]  = wim;
}

// ---------------- scan pass 1 (f32x2 packed, hoisted u broadcasts) -----------------
__global__ __launch_bounds__(256) void scan_part1(const float* __restrict__ x) {
    int tid  = threadIdx.x;
    int gid  = blockIdx.x * 32 + (tid >> 3);
    int lane = tid & 7;
    int seg  = gid % (SEG - 1);
    int rem  = gid / (SEG - 1);
    int h = rem & (HDIM - 1);
    int b = rem >> 9;

    uint64_t wre01[4], wim01[4], nwim01[4], sre01[4], sim01[4];
    int base = h * NST + lane * 8;
#pragma unroll
    for (int p = 0; p < 4; p++) {
        float w0 = g_wre[base + 2*p], w1 = g_wre[base + 2*p + 1];
        float i0 = g_wim[base + 2*p], i1 = g_wim[base + 2*p + 1];
        wre01[p]  = pk2(w0, w1);
        wim01[p]  = pk2(i0, i1);
        nwim01[p] = pk2(-i0, -i1);
        sre01[p] = 0; sim01[p] = 0;
    }
    const float* xp = x + ((size_t)b * LSEQ + seg * SEGT) * HDIM + h;

    float ucur = __ldg(xp + (size_t)lane * HDIM);
    for (int l0 = 0; l0 < SEGT; l0 += 8) {
        int ln = l0 + 8 + lane; if (ln > SEGT - 1) ln = SEGT - 1;
        float unext = __ldg(xp + (size_t)ln * HDIM);

        // hoisted, independent broadcasts — pipeline instead of per-step serialization
        float ub[8];
#pragma unroll
        for (int k = 0; k < 8; k++) ub[k] = __shfl_sync(0xffffffffu, ucur, k, 8);

#pragma unroll
        for (int k = 0; k < 8; k++) {
            uint64_t u2 = pk2(ub[k], ub[k]);
#pragma unroll
            for (int p = 0; p < 4; p++) {
                uint64_t nr = fma2(wre01[p], sre01[p], fma2(nwim01[p], sim01[p], u2));
                uint64_t ni = fma2(wim01[p], sre01[p], mul2(wre01[p], sim01[p]));
                sre01[p] = nr; sim01[p] = ni;
            }
        }
        ucur = unext;
    }

    size_t ob = (((size_t)(b * HDIM + h) * SEG) + seg) * NST + lane * 8;
#pragma unroll
    for (int p = 0; p < 4; p++) {
        float r0, r1, i0, i1;
        upk2(sre01[p], r0, r1);
        upk2(sim01[p], i0, i1);
        g_sendre[ob + 2*p] = r0; g_sendre[ob + 2*p + 1] = r1;
        g_sendim[ob + 2*p] = i0; g_sendim[ob + 2*p + 1] = i1;
    }
}

// ---------------- combine ----------------------------------------------------------
__global__ __launch_bounds__(256) void scan_combine() {
    int idx = blockIdx.x * blockDim.x + threadIdx.x;
    int n = idx & (NST - 1);
    int rem = idx >> 6;
    int h = rem & (HDIM - 1);
    int b = rem >> 9;
    float wTre = g_wTre[h * NST + n];
    float wTim = g_wTim[h * NST + n];
    float cr = 0.0f, ci = 0.0f;
    size_t base = ((size_t)(b * HDIM + h) * SEG) * NST + n;
#pragma unroll
    for (int j = 0; j < SEG; j++) {
        g_carre[base + (size_t)j * NST] = cr;
        g_carim[base + (size_t)j * NST] = ci;
        if (j < SEG - 1) {
            float er = g_sendre[base + (size_t)j * NST];
            float ei = g_sendim[base + (size_t)j * NST];
            float nr = fmaf(wTre, cr, fmaf(-wTim, ci, er));
            float ni = fmaf(wTim, cr, fmaf(wTre, ci, ei));
            cr = nr; ci = ni;
        }
    }
}

// ---------------- scan pass 2 (hoisted u broadcasts + transpose reduce) ------------
__global__ __launch_bounds__(256) void scan_part2(const float* __restrict__ x,
                                                  const float* __restrict__ Dskip,
                                                  bf16* __restrict__ yh,
                                                  bf16* __restrict__ yl) {
    int tid  = threadIdx.x;
    int gid  = blockIdx.x * 32 + (tid >> 3);
    int lane = tid & 7;
    int seg  = gid & (SEG - 1);
    int rem  = gid >> 4;
    int h = rem & (HDIM - 1);
    int b = rem >> 9;

    uint64_t wre01[4], wim01[4], nwim01[4], cre01[4], ncim01[4], sre01[4], sim01[4];
    int base = h * NST + lane * 8;
    size_t cb = (((size_t)(b * HDIM + h) * SEG) + seg) * NST + lane * 8;
#pragma unroll
    for (int p = 0; p < 4; p++) {
        float w0 = g_wre[base + 2*p], w1 = g_wre[base + 2*p + 1];
        float i0 = g_wim[base + 2*p], i1 = g_wim[base + 2*p + 1];
        float c0 = g_ctre[base + 2*p], c1 = g_ctre[base + 2*p + 1];
        float d0 = g_ctim[base + 2*p], d1 = g_ctim[base + 2*p + 1];
        wre01[p]  = pk2(w0, w1);
        wim01[p]  = pk2(i0, i1);
        nwim01[p] = pk2(-i0, -i1);
        cre01[p]  = pk2(c0, c1);
        ncim01[p] = pk2(-d0, -d1);
        sre01[p] = pk2(g_carre[cb + 2*p], g_carre[cb + 2*p + 1]);
        sim01[p] = pk2(g_carim[cb + 2*p], g_carim[cb + 2*p + 1]);
    }
    float Dv = Dskip[h];
    const float* xp = x + ((size_t)b * LSEQ + seg * SEGT) * HDIM + h;
    size_t orow = ((size_t)b * LSEQ + seg * SEGT) * HDIM + h;

    bool l1 = (lane & 1), l2 = (lane & 2), l4 = (lane & 4);

    float ucur = __ldg(xp + (size_t)lane * HDIM);
    for (int l0 = 0; l0 < SEGT; l0 += 8) {
        int ln = l0 + 8 + lane; if (ln > SEGT - 1) ln = SEGT - 1;
        float unext = __ldg(xp + (size_t)ln * HDIM);

        // hoisted independent broadcasts; buf is reused for per-step partials
        float buf[8];
#pragma unroll
        for (int k = 0; k < 8; k++) buf[k] = __shfl_sync(0xffffffffu, ucur, k, 8);

#pragma unroll
        for (int k = 0; k < 8; k++) {
            uint64_t u2 = pk2(buf[k], buf[k]);
            uint64_t accR, accI;
            {
                uint64_t nr = fma2(wre01[0], sre01[0], fma2(nwim01[0], sim01[0], u2));
                uint64_t ni = fma2(wim01[0], sre01[0], mul2(wre01[0], sim01[0]));
                sre01[0] = nr; sim01[0] = ni;
                accR = mul2(cre01[0], nr);
                accI = mul2(ncim01[0], ni);
            }
#pragma unroll
            for (int p = 1; p < 4; p++) {
                uint64_t nr = fma2(wre01[p], sre01[p], fma2(nwim01[p], sim01[p], u2));
                uint64_t ni = fma2(wim01[p], sre01[p], mul2(wre01[p], sim01[p]));
                sre01[p] = nr; sim01[p] = ni;
                accR = fma2(cre01[p], nr, accR);
                accI = fma2(ncim01[p], ni, accI);
            }
            uint64_t t = add2(accR, accI);
            float ta, tb; upk2(t, ta, tb);
            buf[k] = ta + tb;            // overwrite consumed u with partial
        }

        // recursive-halving transpose reduce: lane k ends with sum over states of step k
        float q[4], r[2], sfin;
#pragma unroll
        for (int j = 0; j < 4; j++) {
            float a = buf[2*j], bb = buf[2*j + 1];
            float sendv = l1 ? a : bb;
            float keepv = l1 ? bb : a;
            q[j] = keepv + __shfl_xor_sync(0xffffffffu, sendv, 1, 8);
        }
#pragma unroll
        for (int j = 0; j < 2; j++) {
            float a = q[2*j], bb = q[2*j + 1];
            float sendv = l2 ? a : bb;
            float keepv = l2 ? bb : a;
            r[j] = keepv + __shfl_xor_sync(0xffffffffu, sendv, 2, 8);
        }
        {
            float sendv = l4 ? r[0] : r[1];
            float keepv = l4 ? r[1] : r[0];
            sfin = keepv + __shfl_xor_sync(0xffffffffu, sendv, 4, 8);
        }

        // lane k outputs step l0+k; its own ucur IS u[l0+k]
        float vv = fmaf(2.0f, sfin, Dv * ucur);
        float c = 0.7978845608028654f * (vv + 0.044715f * vv * vv * vv);
        float gv = vv / (1.0f + __expf(-2.0f * c));
        bf16 hh, ll; split1(gv, hh, ll);
        size_t o = orow + (size_t)(l0 + lane) * HDIM;
        yh[o] = hh;
        yl[o] = ll;

        ucur = unext;
    }
}

// ======================= mma.sync split-bf16 GEMM, cp.async 2-stage, 1 sync/chunk ==
#define LDSB   80
#define TILEB  (128 * LDSB)
#define STAGEB (4 * TILEB)
#define NSTAGE 2
#define GEMM_SMEM (NSTAGE * STAGEB)   // 81920 bytes -> 2 CTAs/SM

__global__ void __launch_bounds__(256, 2)
gemm_mma(const bf16* __restrict__ Ah, const bf16* __restrict__ Al,
         const bf16* __restrict__ Bh, const bf16* __restrict__ Bl,
         const float* __restrict__ bias,
         float* __restrict__ C, bf16* __restrict__ Ch, bf16* __restrict__ Cl,
         int K, int N, int mode) {
    extern __shared__ char smem[];
    uint32_t sbase = smem_u32(smem);
    int tid = threadIdx.x, wid = tid >> 5, lane = tid & 31;
    int row0 = blockIdx.y * 128, col0 = blockIdx.x * 128;
    int wm = wid >> 1, wn = wid & 1;

    float acc[2][8][4];
#pragma unroll
    for (int i = 0; i < 2; i++)
#pragma unroll
        for (int j = 0; j < 8; j++)
#pragma unroll
            for (int q = 0; q < 4; q++) acc[i][j][q] = 0.0f;

    int lr = tid >> 1;
    int lc = (tid & 1) * 16;
    const bf16* aph = Ah + (size_t)(row0 + lr) * K + lc;
    const bf16* apl = Al + (size_t)(row0 + lr) * K + lc;
    const bf16* bph = Bh + (size_t)(col0 + lr) * K + lc;
    const bf16* bpl = Bl + (size_t)(col0 + lr) * K + lc;
    uint32_t soff = (uint32_t)(lr * LDSB + lc * 2);

    int nch = K / 32;

    auto issue = [&](int c, int s) {
        uint32_t st = sbase + (uint32_t)s * STAGEB;
        int go = c * 32;
        uint32_t ah = st + soff;
        CP_ASYNC16(ah,              aph + go);
        CP_ASYNC16(ah + 16,         aph + go + 8);
        CP_ASYNC16(ah + TILEB,      apl + go);
        CP_ASYNC16(ah + TILEB + 16, apl + go + 8);
        uint32_t bh = st + 2 * TILEB + soff;
        CP_ASYNC16(bh,              bph + go);
        CP_ASYNC16(bh + 16,         bph + go + 8);
        CP_ASYNC16(bh + TILEB,      bpl + go);
        CP_ASYNC16(bh + TILEB + 16, bpl + go + 8);
    };

    issue(0, 0);
    CP_COMMIT();

    int r_lm = (lane & 7) + ((lane >> 3) & 1) * 8;
    int k_lm = ((lane >> 4) & 1) * 8;

    for (int c = 0; c < nch; ++c) {
        CP_WAIT(0);
        __syncthreads();
        if (c + 1 < nch) {
            issue(c + 1, (c + 1) & 1);
            CP_COMMIT();
        }

        uint32_t st = sbase + (uint32_t)(c & 1) * STAGEB;
        uint32_t ahs = st;
        uint32_t bhs = st + 2 * TILEB;

#pragma unroll
        for (int ks = 0; ks < 2; ++ks) {
            int kcol = ks * 16 + k_lm;
            uint32_t afh[2][4], afl[2][4];
#pragma unroll
            for (int mi = 0; mi < 2; ++mi) {
                int m = wm * 32 + mi * 16 + r_lm;
                uint32_t ad = ahs + (uint32_t)(m * LDSB + kcol * 2);
                ldmatrix_x4(afh[mi], ad);
                ldmatrix_x4(afl[mi], ad + TILEB);
            }
#pragma unroll
            for (int nj = 0; nj < 4; ++nj) {
                uint32_t bfh[4], bfl[4];
                int n = wn * 64 + nj * 16 + r_lm;
                uint32_t bd = bhs + (uint32_t)(n * LDSB + kcol * 2);
                ldmatrix_x4(bfh, bd);
                ldmatrix_x4(bfl, bd + TILEB);
#pragma unroll
                for (int mi = 0; mi < 2; ++mi)
#pragma unroll
                    for (int h = 0; h < 2; ++h) {
                        float* cc = acc[mi][nj * 2 + h];
                        mma_bf16(cc, afh[mi], bfh[h], bfh[2 + h]);
                        mma_bf16(cc, afh[mi], bfl[h], bfl[2 + h]);
                        mma_bf16(cc, afl[mi], bfh[h], bfh[2 + h]);
                    }
            }
        }
    }

    int tg = lane >> 2, tq = lane & 3;
#pragma unroll
    for (int mi = 0; mi < 2; ++mi) {
        int r = row0 + wm * 32 + mi * 16 + tg;
#pragma unroll
        for (int ni = 0; ni < 8; ++ni) {
            int cix = col0 + wn * 64 + ni * 8 + tq * 2;
            float b0 = bias[cix], b1 = bias[cix + 1];
            float v0 = acc[mi][ni][0] + b0, v1 = acc[mi][ni][1] + b1;
            float v2 = acc[mi][ni][2] + b0, v3 = acc[mi][ni][3] + b1;
            if (mode == 0) {
                *(float2*)(C + (size_t)r * N + cix) = make_float2(v0, v1);
                *(float2*)(C + (size_t)(r + 8) * N + cix) = make_float2(v2, v3);
            } else {
                v0 = fmaxf(v0, 0.0f); v1 = fmaxf(v1, 0.0f);
                v2 = fmaxf(v2, 0.0f); v3 = fmaxf(v3, 0.0f);
                bf16 h0, l0, h1, l1;
                split1(v0, h0, l0); split1(v1, h1, l1);
                *(bf162*)(Ch + (size_t)r * N + cix) = bf162(h0, h1);
                *(bf162*)(Cl + (size_t)r * N + cix) = bf162(l0, l1);
                split1(v2, h0, l0); split1(v3, h1, l1);
                *(bf162*)(Ch + (size_t)(r + 8) * N + cix) = bf162(h0, h1);
                *(bf162*)(Cl + (size_t)(r + 8) * N + cix) = bf162(l0, l1);
            }
        }
    }
}

// ---------------- block reduce helper ---------------------------------------------
__device__ __forceinline__ float2 block_reduce_2(float a, float b) {
    unsigned m = 0xffffffffu;
#pragma unroll
    for (int o = 16; o > 0; o >>= 1) {
        a += __shfl_down_sync(m, a, o);
        b += __shfl_down_sync(m, b, o);
    }
    __shared__ float sa[4], sb[4];
    int w = threadIdx.x >> 5, lane = threadIdx.x & 31;
    if (lane == 0) { sa[w] = a; sb[w] = b; }
    __syncthreads();
    if (threadIdx.x == 0) {
        float ta = sa[0] + sa[1] + sa[2] + sa[3];
        float tb = sb[0] + sb[1] + sb[2] + sb[3];
        sa[0] = ta; sb[0] = tb;
    }
    __syncthreads();
    return make_float2(sa[0], sb[0]);
}

// ---------------- GLU + residual + LN1 ---------------------------------------------
__global__ __launch_bounds__(128) void glu_ln_kernel(const float* __restrict__ z,
                                                     const float* __restrict__ x,
                                                     const float* __restrict__ g1,
                                                     const float* __restrict__ b1,
                                                     float* __restrict__ xln,
                                                     bf16* __restrict__ xh,
                                                     bf16* __restrict__ xl) {
    int row = blockIdx.x, tid = threadIdx.x;
    const float* zr = z + (size_t)row * (2 * HDIM);
    const float* xr = x + (size_t)row * HDIM;
    float v[4], s = 0.0f, s2 = 0.0f;
#pragma unroll
    for (int i = 0; i < 4; i++) {
        int c = tid + i * 128;
        float a = zr[c], g = zr[c + HDIM];
        float val = xr[c] + a / (1.0f + __expf(-g));
        v[i] = val; s += val; s2 += val * val;
    }
    float2 tot = block_reduce_2(s, s2);
    float mu = tot.x * (1.0f / HDIM);
    float var = tot.y * (1.0f / HDIM) - mu * mu;
    float rstd = rsqrtf(var + 1e-5f);
#pragma unroll
    for (int i = 0; i < 4; i++) {
        int c = tid + i * 128;
        float o = (v[i] - mu) * rstd * g1[c] + b1[c];
        xln[(size_t)row * HDIM + c] = o;
        bf16 hh, ll; split1(o, hh, ll);
        xh[(size_t)row * HDIM + c] = hh;
        xl[(size_t)row * HDIM + c] = ll;
    }
}

// ---------------- residual + LN2 ---------------------------------------------------
__global__ __launch_bounds__(128) void final_ln_kernel(const float* __restrict__ xln,
                                                       const float* __restrict__ y2,
                                                       const float* __restrict__ g2,
                                                       const float* __restrict__ b2,
                                                       float* __restrict__ out) {
    int row = blockIdx.x, tid = threadIdx.x;
    const float* a = xln + (size_t)row * HDIM;
    const float* b = y2 + (size_t)row * HDIM;
    float v[4], s = 0.0f, s2 = 0.0f;
#pragma unroll
    for (int i = 0; i < 4; i++) {
        int c = tid + i * 128;
        float val = a[c] + b[c];
        v[i] = val; s += val; s2 += val * val;
    }
    float2 tot = block_reduce_2(s, s2);
    float mu = tot.x * (1.0f / HDIM);
    float var = tot.y * (1.0f / HDIM) - mu * mu;
    float rstd = rsqrtf(var + 1e-5f);
#pragma unroll
    for (int i = 0; i < 4; i++) {
        int c = tid + i * 128;
        out[(size_t)row * HDIM + c] = (v[i] - mu) * rstd * g2[c] + b2[c];
    }
}

// ---------------- launch ------------------------------------------------------------
extern "C" void kernel_launch(void* const* d_in, const int* in_sizes, int n_in,
                              void* d_out, int out_size) {
    const float* x      = (const float*)d_in[0];
    const float* log_dt = (const float*)d_in[1];
    const float* A_re   = (const float*)d_in[2];
    const float* A_im   = (const float*)d_in[3];
    const float* C_re   = (const float*)d_in[4];
    const float* C_im   = (const float*)d_in[5];
    const float* D_skip = (const float*)d_in[6];
    const float* W_out  = (const float*)d_in[7];
    const float* b_out  = (const float*)d_in[8];
    const float* g1     = (const float*)d_in[9];
    const float* beta1  = (const float*)d_in[10];
    const float* g2     = (const float*)d_in[11];
    const float* beta2  = (const float*)d_in[12];
    const float* W1     = (const float*)d_in[13];
    const float* bc1    = (const float*)d_in[14];
    const float* W2     = (const float*)d_in[15];
    const float* bc2    = (const float*)d_in[16];
    float* out = (float*)d_out;

    bf16 *yh, *yl, *xh, *xl, *y1h, *y1l;
    bf16 *wouth, *woutl, *w1h, *w1l, *w2h, *w2l;
    float *z, *xln, *y2;
    cudaGetSymbolAddress((void**)&yh,  g_yh);
    cudaGetSymbolAddress((void**)&yl,  g_yl);
    cudaGetSymbolAddress((void**)&z,   g_z);
    cudaGetSymbolAddress((void**)&xln, g_xln);
    cudaGetSymbolAddress((void**)&xh,  g_xh);
    cudaGetSymbolAddress((void**)&xl,  g_xl);
    cudaGetSymbolAddress((void**)&y1h, g_y1h);
    cudaGetSymbolAddress((void**)&y1l, g_y1l);
    cudaGetSymbolAddress((void**)&y2,  g_y2);
    cudaGetSymbolAddress((void**)&wouth, g_wouth);
    cudaGetSymbolAddress((void**)&woutl, g_woutl);
    cudaGetSymbolAddress((void**)&w1h, g_w1h);
    cudaGetSymbolAddress((void**)&w1l, g_w1l);
    cudaGetSymbolAddress((void**)&w2h, g_w2h);
    cudaGetSymbolAddress((void**)&w2l, g_w2l);

    cudaFuncSetAttribute(gemm_mma, cudaFuncAttributeMaxDynamicSharedMemorySize, GEMM_SMEM);

    precompute_kernel<<<HDIM, NST>>>(log_dt, A_re, A_im, C_re, C_im);

    scan_part1<<<(BSZ * HDIM * (SEG - 1)) / 32, 256>>>(x);
    scan_combine<<<(BSZ * HDIM * NST) / 256, 256>>>();
    scan_part2<<<(BSZ * HDIM * SEG) / 32, 256>>>(x, D_skip, yh, yl);

    split_all_kernel<<<(4 * HDIM * HDIM + 255) / 256, 256>>>(W_out, W1, W2);

    gemm_mma<<<dim3((2 * HDIM) / 128, ROWS / 128), 256, GEMM_SMEM>>>(
        yh, yl, wouth, woutl, b_out, z, nullptr, nullptr, HDIM, 2 * HDIM, 0);

    glu_ln_kernel<<<ROWS, 128>>>(z, x, g1, beta1, xln, xh, xl);

    gemm_mma<<<dim3(HDIM / 128, ROWS / 128), 256, GEMM_SMEM>>>(
        xh, xl, w1h, w1l, bc1, nullptr, y1h, y1l, HDIM, HDIM, 1);

    gemm_mma<<<dim3(HDIM / 128, ROWS / 128), 256, GEMM_SMEM>>>(
        y1h, y1l, w2h, w2l, bc2, y2, nullptr, nullptr, HDIM, HDIM, 0);

    final_ln_kernel<<<ROWS, 128>>>(xln, y2, g2, beta2, out);
}

// round 10
// speedup vs baseline: 1.0305x; 1.0305x over previous
#include <cuda_runtime.h>
#include <cuda_bf16.h>
#include <math.h>
#include <stdint.h>

#define BSZ   8
#define LSEQ  2048
#define HDIM  512
#define NST   64
#define ROWS  (BSZ*LSEQ)      // 16384
#define SEG   16
#define SEGT  (LSEQ/SEG)      // 128

typedef __nv_bfloat16 bf16;
typedef __nv_bfloat162 bf162;

// ---------------- scratch ----------------------------------------------------------
__device__ float g_wre[HDIM*NST];
__device__ float g_wim[HDIM*NST];
__device__ float g_wTre[HDIM*NST];
__device__ float g_wTim[HDIM*NST];
__device__ float g_ctre[HDIM*NST];
__device__ float g_ctim[HDIM*NST];

__device__ float g_xT[(size_t)ROWS*HDIM];             // x transposed to (B, H, L)

__device__ float g_sendre[(size_t)BSZ*HDIM*SEG*NST];
__device__ float g_sendim[(size_t)BSZ*HDIM*SEG*NST];
__device__ float g_carre [(size_t)BSZ*HDIM*SEG*NST];
__device__ float g_carim [(size_t)BSZ*HDIM*SEG*NST];

__device__ bf16  g_yh [(size_t)ROWS*HDIM];
__device__ bf16  g_yl [(size_t)ROWS*HDIM];
__device__ float g_z  [(size_t)ROWS*2*HDIM];
__device__ float g_xln[(size_t)ROWS*HDIM];
__device__ bf16  g_xh [(size_t)ROWS*HDIM];
__device__ bf16  g_xl [(size_t)ROWS*HDIM];
__device__ bf16  g_y1h[(size_t)ROWS*HDIM];
__device__ bf16  g_y1l[(size_t)ROWS*HDIM];
__device__ float g_y2 [(size_t)ROWS*HDIM];

__device__ bf16 g_wouth[2*HDIM*HDIM];
__device__ bf16 g_woutl[2*HDIM*HDIM];
__device__ bf16 g_w1h[HDIM*HDIM];
__device__ bf16 g_w1l[HDIM*HDIM];
__device__ bf16 g_w2h[HDIM*HDIM];
__device__ bf16 g_w2l[HDIM*HDIM];

// =============================== helpers =========================================
__device__ __forceinline__ uint32_t smem_u32(const void* p) {
    uint32_t a;
    asm("{ .reg .u64 t; cvta.to.shared.u64 t, %1; cvt.u32.u64 %0, t; }" : "=r"(a) : "l"(p));
    return a;
}

__device__ __forceinline__ void ldmatrix_x4(uint32_t* r, uint32_t addr) {
    asm volatile("ldmatrix.sync.aligned.m8n8.x4.shared.b16 {%0,%1,%2,%3}, [%4];"
        : "=r"(r[0]), "=r"(r[1]), "=r"(r[2]), "=r"(r[3]) : "r"(addr));
}

__device__ __forceinline__ void mma_bf16(float* c, const uint32_t* a,
                                         uint32_t b0, uint32_t b1) {
    asm volatile("mma.sync.aligned.m16n8k16.row.col.f32.bf16.bf16.f32 "
        "{%0,%1,%2,%3}, {%4,%5,%6,%7}, {%8,%9}, {%0,%1,%2,%3};"
        : "+f"(c[0]), "+f"(c[1]), "+f"(c[2]), "+f"(c[3])
        : "r"(a[0]), "r"(a[1]), "r"(a[2]), "r"(a[3]), "r"(b0), "r"(b1));
}

#define CP_ASYNC16(saddr, gaddr) \
    asm volatile("cp.async.cg.shared.global [%0], [%1], 16;" \
                 :: "r"(saddr), "l"(gaddr) : "memory")
#define CP_COMMIT() asm volatile("cp.async.commit_group;" ::: "memory")
#define CP_WAIT(n)  asm volatile("cp.async.wait_group %0;" :: "n"(n) : "memory")

__device__ __forceinline__ void split1(float v, bf16& h, bf16& l) {
    h = __float2bfloat16(v);
    l = __float2bfloat16(v - __bfloat162float(h));
}

// ---- packed f32x2 ops (Blackwell) ----
__device__ __forceinline__ uint64_t pk2(float lo, float hi) {
    uint64_t r; asm("mov.b64 %0, {%1,%2};" : "=l"(r) : "f"(lo), "f"(hi)); return r;
}
__device__ __forceinline__ void upk2(uint64_t v, float& lo, float& hi) {
    asm("mov.b64 {%0,%1}, %2;" : "=f"(lo), "=f"(hi) : "l"(v));
}
__device__ __forceinline__ uint64_t fma2(uint64_t a, uint64_t b, uint64_t c) {
    uint64_t d; asm("fma.rn.f32x2 %0, %1, %2, %3;" : "=l"(d) : "l"(a), "l"(b), "l"(c)); return d;
}
__device__ __forceinline__ uint64_t mul2(uint64_t a, uint64_t b) {
    uint64_t d; asm("mul.rn.f32x2 %0, %1, %2;" : "=l"(d) : "l"(a), "l"(b)); return d;
}
__device__ __forceinline__ uint64_t add2(uint64_t a, uint64_t b) {
    uint64_t d; asm("add.rn.f32x2 %0, %1, %2;" : "=l"(d) : "l"(a), "l"(b)); return d;
}

// ---------------- x transpose: (B,L,H) -> (B,H,L) ---------------------------------
__global__ __launch_bounds__(256) void transpose_kernel(const float* __restrict__ x,
                                                        float* __restrict__ xT) {
    __shared__ float tile[32][33];
    int b  = blockIdx.z;
    int l0 = blockIdx.x * 32, h0 = blockIdx.y * 32;
    int tx = threadIdx.x & 31, ty = threadIdx.x >> 5;    // 32 x 8
    const float* xp = x + (size_t)b * LSEQ * HDIM;
#pragma unroll
    for (int i = 0; i < 32; i += 8)
        tile[ty + i][tx] = xp[(size_t)(l0 + ty + i) * HDIM + h0 + tx];
    __syncthreads();
    float* op = xT + (size_t)b * HDIM * LSEQ;
#pragma unroll
    for (int i = 0; i < 32; i += 8)
        op[(size_t)(h0 + ty + i) * LSEQ + l0 + tx] = tile[tx][ty + i];
}

// ---------------- weight split -----------------------------------------------------
__global__ void split_all_kernel(const float* __restrict__ wout,
                                 const float* __restrict__ w1,
                                 const float* __restrict__ w2) {
    int i = blockIdx.x * blockDim.x + threadIdx.x;
    const int n1 = 2 * HDIM * HDIM;
    const int n2 = HDIM * HDIM;
    if (i < n1) {
        bf16 h, l; split1(wout[i], h, l);
        g_wouth[i] = h; g_woutl[i] = l;
    } else if (i < n1 + n2) {
        int j = i - n1;
        bf16 h, l; split1(w1[j], h, l);
        g_w1h[j] = h; g_w1l[j] = l;
    } else {
        int j = i - n1 - n2;
        bf16 h, l; split1(w2[j], h, l);
        g_w2h[j] = h; g_w2l[j] = l;
    }
}

// ---------------- precompute -------------------------------------------------------
__global__ void precompute_kernel(const float* __restrict__ log_dt,
                                  const float* __restrict__ Are,
                                  const float* __restrict__ Aim,
                                  const float* __restrict__ Cre,
                                  const float* __restrict__ Cim) {
    int h = blockIdx.x, n = threadIdx.x;
    int idx = h * NST + n;
    float dt = expf(log_dt[h]);
    float ar = Are[idx] * dt;
    float ai = Aim[idx] * dt;
    float e  = expf(ar);
    float sb, cb;
    sincosf(ai, &sb, &cb);
    float wre = e * cb, wim = e * sb;
    float eT = expf(ar * (float)SEGT);
    float sT, cT;
    sincosf(ai * (float)SEGT, &sT, &cT);
    g_wTre[idx] = eT * cT;
    g_wTim[idx] = eT * sT;

    float Ere = wre - 1.0f, Eim = wim;
    float Ar = Are[idx], Ai = Aim[idx];
    float inv = 1.0f / (Ar * Ar + Ai * Ai);
    float rre = (Ere * Ar + Eim * Ai) * inv;
    float rim = (Eim * Ar - Ere * Ai) * inv;
    float cr = Cre[idx], ci = Cim[idx];
    g_ctre[idx] = cr * rre - ci * rim;
    g_ctim[idx] = cr * rim + ci * rre;
    g_wre[idx]  = wre;
    g_wim[idx]  = wim;
}

// ---------------- scan pass 1 (coalesced u loads from xT) --------------------------
__global__ __launch_bounds__(256) void scan_part1(const float* __restrict__ xT) {
    int tid  = threadIdx.x;
    int gid  = blockIdx.x * 32 + (tid >> 3);
    int lane = tid & 7;
    int seg  = gid % (SEG - 1);
    int rem  = gid / (SEG - 1);
    int h = rem & (HDIM - 1);
    int b = rem >> 9;

    uint64_t wre01[4], wim01[4], nwim01[4], sre01[4], sim01[4];
    int base = h * NST + lane * 8;
#pragma unroll
    for (int p = 0; p < 4; p++) {
        float w0 = g_wre[base + 2*p], w1 = g_wre[base + 2*p + 1];
        float i0 = g_wim[base + 2*p], i1 = g_wim[base + 2*p + 1];
        wre01[p]  = pk2(w0, w1);
        wim01[p]  = pk2(i0, i1);
        nwim01[p] = pk2(-i0, -i1);
        sre01[p] = 0; sim01[p] = 0;
    }
    const float* xp = xT + ((size_t)(b * HDIM + h)) * LSEQ + seg * SEGT;

    float ucur = __ldg(xp + lane);
    for (int l0 = 0; l0 < SEGT; l0 += 8) {
        int ln = l0 + 8 + lane; if (ln > SEGT - 1) ln = SEGT - 1;
        float unext = __ldg(xp + ln);

        float ub[8];
#pragma unroll
        for (int k = 0; k < 8; k++) ub[k] = __shfl_sync(0xffffffffu, ucur, k, 8);

#pragma unroll
        for (int k = 0; k < 8; k++) {
            uint64_t u2 = pk2(ub[k], ub[k]);
#pragma unroll
            for (int p = 0; p < 4; p++) {
                uint64_t nr = fma2(wre01[p], sre01[p], fma2(nwim01[p], sim01[p], u2));
                uint64_t ni = fma2(wim01[p], sre01[p], mul2(wre01[p], sim01[p]));
                sre01[p] = nr; sim01[p] = ni;
            }
        }
        ucur = unext;
    }

    size_t ob = (((size_t)(b * HDIM + h) * SEG) + seg) * NST + lane * 8;
#pragma unroll
    for (int p = 0; p < 4; p++) {
        float r0, r1, i0, i1;
        upk2(sre01[p], r0, r1);
        upk2(sim01[p], i0, i1);
        g_sendre[ob + 2*p] = r0; g_sendre[ob + 2*p + 1] = r1;
        g_sendim[ob + 2*p] = i0; g_sendim[ob + 2*p + 1] = i1;
    }
}

// ---------------- combine ----------------------------------------------------------
__global__ __launch_bounds__(256) void scan_combine() {
    int idx = blockIdx.x * blockDim.x + threadIdx.x;
    int n = idx & (NST - 1);
    int rem = idx >> 6;
    int h = rem & (HDIM - 1);
    int b = rem >> 9;
    float wTre = g_wTre[h * NST + n];
    float wTim = g_wTim[h * NST + n];
    float cr = 0.0f, ci = 0.0f;
    size_t base = ((size_t)(b * HDIM + h) * SEG) * NST + n;
#pragma unroll
    for (int j = 0; j < SEG; j++) {
        g_carre[base + (size_t)j * NST] = cr;
        g_carim[base + (size_t)j * NST] = ci;
        if (j < SEG - 1) {
            float er = g_sendre[base + (size_t)j * NST];
            float ei = g_sendim[base + (size_t)j * NST];
            float nr = fmaf(wTre, cr, fmaf(-wTim, ci, er));
            float ni = fmaf(wTim, cr, fmaf(wTre, ci, ei));
            cr = nr; ci = ni;
        }
    }
}

// ---------------- scan pass 2 (coalesced u loads + transpose reduce) ---------------
__global__ __launch_bounds__(256) void scan_part2(const float* __restrict__ xT,
                                                  const float* __restrict__ Dskip,
                                                  bf16* __restrict__ yh,
                                                  bf16* __restrict__ yl) {
    int tid  = threadIdx.x;
    int gid  = blockIdx.x * 32 + (tid >> 3);
    int lane = tid & 7;
    int seg  = gid & (SEG - 1);
    int rem  = gid >> 4;
    int h = rem & (HDIM - 1);
    int b = rem >> 9;

    uint64_t wre01[4], wim01[4], nwim01[4], cre01[4], ncim01[4], sre01[4], sim01[4];
    int base = h * NST + lane * 8;
    size_t cb = (((size_t)(b * HDIM + h) * SEG) + seg) * NST + lane * 8;
#pragma unroll
    for (int p = 0; p < 4; p++) {
        float w0 = g_wre[base + 2*p], w1 = g_wre[base + 2*p + 1];
        float i0 = g_wim[base + 2*p], i1 = g_wim[base + 2*p + 1];
        float c0 = g_ctre[base + 2*p], c1 = g_ctre[base + 2*p + 1];
        float d0 = g_ctim[base + 2*p], d1 = g_ctim[base + 2*p + 1];
        wre01[p]  = pk2(w0, w1);
        wim01[p]  = pk2(i0, i1);
        nwim01[p] = pk2(-i0, -i1);
        cre01[p]  = pk2(c0, c1);
        ncim01[p] = pk2(-d0, -d1);
        sre01[p] = pk2(g_carre[cb + 2*p], g_carre[cb + 2*p + 1]);
        sim01[p] = pk2(g_carim[cb + 2*p], g_carim[cb + 2*p + 1]);
    }
    float Dv = Dskip[h];
    const float* xp = xT + ((size_t)(b * HDIM + h)) * LSEQ + seg * SEGT;
    size_t orow = ((size_t)b * LSEQ + seg * SEGT) * HDIM + h;

    bool l1 = (lane & 1), l2 = (lane & 2), l4 = (lane & 4);

    float ucur = __ldg(xp + lane);
    for (int l0 = 0; l0 < SEGT; l0 += 8) {
        int ln = l0 + 8 + lane; if (ln > SEGT - 1) ln = SEGT - 1;
        float unext = __ldg(xp + ln);

        float buf[8];
#pragma unroll
        for (int k = 0; k < 8; k++) buf[k] = __shfl_sync(0xffffffffu, ucur, k, 8);

#pragma unroll
        for (int k = 0; k < 8; k++) {
            uint64_t u2 = pk2(buf[k], buf[k]);
            uint64_t accR, accI;
            {
                uint64_t nr = fma2(wre01[0], sre01[0], fma2(nwim01[0], sim01[0], u2));
                uint64_t ni = fma2(wim01[0], sre01[0], mul2(wre01[0], sim01[0]));
                sre01[0] = nr; sim01[0] = ni;
                accR = mul2(cre01[0], nr);
                accI = mul2(ncim01[0], ni);
            }
#pragma unroll
            for (int p = 1; p < 4; p++) {
                uint64_t nr = fma2(wre01[p], sre01[p], fma2(nwim01[p], sim01[p], u2));
                uint64_t ni = fma2(wim01[p], sre01[p], mul2(wre01[p], sim01[p]));
                sre01[p] = nr; sim01[p] = ni;
                accR = fma2(cre01[p], nr, accR);
                accI = fma2(ncim01[p], ni, accI);
            }
            uint64_t t = add2(accR, accI);
            float ta, tb; upk2(t, ta, tb);
            buf[k] = ta + tb;
        }

        // recursive-halving transpose reduce: lane k ends with sum over states of step k
        float q[4], r[2], sfin;
#pragma unroll
        for (int j = 0; j < 4; j++) {
            float a = buf[2*j], bb = buf[2*j + 1];
            float sendv = l1 ? a : bb;
            float keepv = l1 ? bb : a;
            q[j] = keepv + __shfl_xor_sync(0xffffffffu, sendv, 1, 8);
        }
#pragma unroll
        for (int j = 0; j < 2; j++) {
            float a = q[2*j], bb = q[2*j + 1];
            float sendv = l2 ? a : bb;
            float keepv = l2 ? bb : a;
            r[j] = keepv + __shfl_xor_sync(0xffffffffu, sendv, 2, 8);
        }
        {
            float sendv = l4 ? r[0] : r[1];
            float keepv = l4 ? r[1] : r[0];
            sfin = keepv + __shfl_xor_sync(0xffffffffu, sendv, 4, 8);
        }

        float vv = fmaf(2.0f, sfin, Dv * ucur);
        float c = 0.7978845608028654f * (vv + 0.044715f * vv * vv * vv);
        float gv = vv / (1.0f + __expf(-2.0f * c));
        bf16 hh, ll; split1(gv, hh, ll);
        size_t o = orow + (size_t)(l0 + lane) * HDIM;
        yh[o] = hh;
        yl[o] = ll;

        ucur = unext;
    }
}

// ======================= mma.sync split-bf16 GEMM, cp.async 2-stage ================
#define LDSB   80
#define TILEB  (128 * LDSB)
#define STAGEB (4 * TILEB)
#define NSTAGE 2
#define GEMM_SMEM (NSTAGE * STAGEB)   // 81920 bytes -> 2 CTAs/SM

__global__ void __launch_bounds__(256, 2)
gemm_mma(const bf16* __restrict__ Ah, const bf16* __restrict__ Al,
         const bf16* __restrict__ Bh, const bf16* __restrict__ Bl,
         const float* __restrict__ bias,
         float* __restrict__ C, bf16* __restrict__ Ch, bf16* __restrict__ Cl,
         int K, int N, int mode) {
    extern __shared__ char smem[];
    uint32_t sbase = smem_u32(smem);
    int tid = threadIdx.x, wid = tid >> 5, lane = tid & 31;
    int row0 = blockIdx.y * 128, col0 = blockIdx.x * 128;
    int wm = wid >> 1, wn = wid & 1;

    float acc[2][8][4];
#pragma unroll
    for (int i = 0; i < 2; i++)
#pragma unroll
        for (int j = 0; j < 8; j++)
#pragma unroll
            for (int q = 0; q < 4; q++) acc[i][j][q] = 0.0f;

    int lr = tid >> 1;
    int lc = (tid & 1) * 16;
    const bf16* aph = Ah + (size_t)(row0 + lr) * K + lc;
    const bf16* apl = Al + (size_t)(row0 + lr) * K + lc;
    const bf16* bph = Bh + (size_t)(col0 + lr) * K + lc;
    const bf16* bpl = Bl + (size_t)(col0 + lr) * K + lc;
    uint32_t soff = (uint32_t)(lr * LDSB + lc * 2);

    int nch = K / 32;

    auto issue = [&](int c, int s) {
        uint32_t st = sbase + (uint32_t)s * STAGEB;
        int go = c * 32;
        uint32_t ah = st + soff;
        CP_ASYNC16(ah,              aph + go);
        CP_ASYNC16(ah + 16,         aph + go + 8);
        CP_ASYNC16(ah + TILEB,      apl + go);
        CP_ASYNC16(ah + TILEB + 16, apl + go + 8);
        uint32_t bh = st + 2 * TILEB + soff;
        CP_ASYNC16(bh,              bph + go);
        CP_ASYNC16(bh + 16,         bph + go + 8);
        CP_ASYNC16(bh + TILEB,      bpl + go);
        CP_ASYNC16(bh + TILEB + 16, bpl + go + 8);
    };

    issue(0, 0);
    CP_COMMIT();

    int r_lm = (lane & 7) + ((lane >> 3) & 1) * 8;
    int k_lm = ((lane >> 4) & 1) * 8;

    for (int c = 0; c < nch; ++c) {
        CP_WAIT(0);
        __syncthreads();
        if (c + 1 < nch) {
            issue(c + 1, (c + 1) & 1);
            CP_COMMIT();
        }

        uint32_t st = sbase + (uint32_t)(c & 1) * STAGEB;
        uint32_t ahs = st;
        uint32_t bhs = st + 2 * TILEB;

#pragma unroll
        for (int ks = 0; ks < 2; ++ks) {
            int kcol = ks * 16 + k_lm;
            uint32_t afh[2][4], afl[2][4];
#pragma unroll
            for (int mi = 0; mi < 2; ++mi) {
                int m = wm * 32 + mi * 16 + r_lm;
                uint32_t ad = ahs + (uint32_t)(m * LDSB + kcol * 2);
                ldmatrix_x4(afh[mi], ad);
                ldmatrix_x4(afl[mi], ad + TILEB);
            }
#pragma unroll
            for (int nj = 0; nj < 4; ++nj) {
                uint32_t bfh[4], bfl[4];
                int n = wn * 64 + nj * 16 + r_lm;
                uint32_t bd = bhs + (uint32_t)(n * LDSB + kcol * 2);
                ldmatrix_x4(bfh, bd);
                ldmatrix_x4(bfl, bd + TILEB);
#pragma unroll
                for (int mi = 0; mi < 2; ++mi)
#pragma unroll
                    for (int h = 0; h < 2; ++h) {
                        float* cc = acc[mi][nj * 2 + h];
                        mma_bf16(cc, afh[mi], bfh[h], bfh[2 + h]);
                        mma_bf16(cc, afh[mi], bfl[h], bfl[2 + h]);
                        mma_bf16(cc, afl[mi], bfh[h], bfh[2 + h]);
                    }
            }
        }
    }

    int tg = lane >> 2, tq = lane & 3;
#pragma unroll
    for (int mi = 0; mi < 2; ++mi) {
        int r = row0 + wm * 32 + mi * 16 + tg;
#pragma unroll
        for (int ni = 0; ni < 8; ++ni) {
            int cix = col0 + wn * 64 + ni * 8 + tq * 2;
            float b0 = bias[cix], b1 = bias[cix + 1];
            float v0 = acc[mi][ni][0] + b0, v1 = acc[mi][ni][1] + b1;
            float v2 = acc[mi][ni][2] + b0, v3 = acc[mi][ni][3] + b1;
            if (mode == 0) {
                *(float2*)(C + (size_t)r * N + cix) = make_float2(v0, v1);
                *(float2*)(C + (size_t)(r + 8) * N + cix) = make_float2(v2, v3);
            } else {
                v0 = fmaxf(v0, 0.0f); v1 = fmaxf(v1, 0.0f);
                v2 = fmaxf(v2, 0.0f); v3 = fmaxf(v3, 0.0f);
                bf16 h0, l0, h1, l1;
                split1(v0, h0, l0); split1(v1, h1, l1);
                *(bf162*)(Ch + (size_t)r * N + cix) = bf162(h0, h1);
                *(bf162*)(Cl + (size_t)r * N + cix) = bf162(l0, l1);
                split1(v2, h0, l0); split1(v3, h1, l1);
                *(bf162*)(Ch + (size_t)(r + 8) * N + cix) = bf162(h0, h1);
                *(bf162*)(Cl + (size_t)(r + 8) * N + cix) = bf162(l0, l1);
            }
        }
    }
}

// ---------------- block reduce helper ---------------------------------------------
__device__ __forceinline__ float2 block_reduce_2(float a, float b) {
    unsigned m = 0xffffffffu;
#pragma unroll
    for (int o = 16; o > 0; o >>= 1) {
        a += __shfl_down_sync(m, a, o);
        b += __shfl_down_sync(m, b, o);
    }
    __shared__ float sa[4], sb[4];
    int w = threadIdx.x >> 5, lane = threadIdx.x & 31;
    if (lane == 0) { sa[w] = a; sb[w] = b; }
    __syncthreads();
    if (threadIdx.x == 0) {
        float ta = sa[0] + sa[1] + sa[2] + sa[3];
        float tb = sb[0] + sb[1] + sb[2] + sb[3];
        sa[0] = ta; sb[0] = tb;
    }
    __syncthreads();
    return make_float2(sa[0], sb[0]);
}

// ---------------- GLU + residual + LN1 (float4 vectorized) -------------------------
__global__ __launch_bounds__(128) void glu_ln_kernel(const float* __restrict__ z,
                                                     const float* __restrict__ x,
                                                     const float* __restrict__ g1,
                                                     const float* __restrict__ b1,
                                                     float* __restrict__ xln,
                                                     bf16* __restrict__ xh,
                                                     bf16* __restrict__ xl) {
    int row = blockIdx.x, tid = threadIdx.x;
    const float4* zr = (const float4*)(z + (size_t)row * (2 * HDIM));
    const float4* xr = (const float4*)(x + (size_t)row * HDIM);
    float4 a = zr[tid];
    float4 g = zr[tid + 128];
    float4 xv = xr[tid];
    float4 v;
    v.x = xv.x + a.x / (1.0f + __expf(-g.x));
    v.y = xv.y + a.y / (1.0f + __expf(-g.y));
    v.z = xv.z + a.z / (1.0f + __expf(-g.z));
    v.w = xv.w + a.w / (1.0f + __expf(-g.w));
    float s  = v.x + v.y + v.z + v.w;
    float s2 = v.x*v.x + v.y*v.y + v.z*v.z + v.w*v.w;
    float2 tot = block_reduce_2(s, s2);
    float mu = tot.x * (1.0f / HDIM);
    float var = tot.y * (1.0f / HDIM) - mu * mu;
    float rstd = rsqrtf(var + 1e-5f);
    float4 gv = ((const float4*)g1)[tid];
    float4 bv = ((const float4*)b1)[tid];
    float4 o;
    o.x = (v.x - mu) * rstd * gv.x + bv.x;
    o.y = (v.y - mu) * rstd * gv.y + bv.y;
    o.z = (v.z - mu) * rstd * gv.z + bv.z;
    o.w = (v.w - mu) * rstd * gv.w + bv.w;
    ((float4*)(xln + (size_t)row * HDIM))[tid] = o;
    bf16 h0,l0,h1,l1,h2,l2,h3,l3;
    split1(o.x, h0, l0); split1(o.y, h1, l1);
    split1(o.z, h2, l2); split1(o.w, h3, l3);
    bf162* xh2 = (bf162*)(xh + (size_t)row * HDIM);
    bf162* xl2 = (bf162*)(xl + (size_t)row * HDIM);
    xh2[tid*2]   = bf162(h0, h1);
    xh2[tid*2+1] = bf162(h2, h3);
    xl2[tid*2]   = bf162(l0, l1);
    xl2[tid*2+1] = bf162(l2, l3);
}

// ---------------- residual + LN2 (float4 vectorized) -------------------------------
__global__ __launch_bounds__(128) void final_ln_kernel(const float* __restrict__ xln,
                                                       const float* __restrict__ y2,
                                                       const float* __restrict__ g2,
                                                       const float* __restrict__ b2,
                                                       float* __restrict__ out) {
    int row = blockIdx.x, tid = threadIdx.x;
    float4 a = ((const float4*)(xln + (size_t)row * HDIM))[tid];
    float4 b = ((const float4*)(y2  + (size_t)row * HDIM))[tid];
    float4 v;
    v.x = a.x + b.x; v.y = a.y + b.y; v.z = a.z + b.z; v.w = a.w + b.w;
    float s  = v.x + v.y + v.z + v.w;
    float s2 = v.x*v.x + v.y*v.y + v.z*v.z + v.w*v.w;
    float2 tot = block_reduce_2(s, s2);
    float mu = tot.x * (1.0f / HDIM);
    float var = tot.y * (1.0f / HDIM) - mu * mu;
    float rstd = rsqrtf(var + 1e-5f);
    float4 gv = ((const float4*)g2)[tid];
    float4 bv = ((const float4*)b2)[tid];
    float4 o;
    o.x = (v.x - mu) * rstd * gv.x + bv.x;
    o.y = (v.y - mu) * rstd * gv.y + bv.y;
    o.z = (v.z - mu) * rstd * gv.z + bv.z;
    o.w = (v.w - mu) * rstd * gv.w + bv.w;
    ((float4*)(out + (size_t)row * HDIM))[tid] = o;
}

// ---------------- launch ------------------------------------------------------------
extern "C" void kernel_launch(void* const* d_in, const int* in_sizes, int n_in,
                              void* d_out, int out_size) {
    const float* x      = (const float*)d_in[0];
    const float* log_dt = (const float*)d_in[1];
    const float* A_re   = (const float*)d_in[2];
    const float* A_im   = (const float*)d_in[3];
    const float* C_re   = (const float*)d_in[4];
    const float* C_im   = (const float*)d_in[5];
    const float* D_skip = (const float*)d_in[6];
    const float* W_out  = (const float*)d_in[7];
    const float* b_out  = (const float*)d_in[8];
    const float* g1     = (const float*)d_in[9];
    const float* beta1  = (const float*)d_in[10];
    const float* g2     = (const float*)d_in[11];
    const float* beta2  = (const float*)d_in[12];
    const float* W1     = (const float*)d_in[13];
    const float* bc1    = (const float*)d_in[14];
    const float* W2     = (const float*)d_in[15];
    const float* bc2    = (const float*)d_in[16];
    float* out = (float*)d_out;

    bf16 *yh, *yl, *xh, *xl, *y1h, *y1l;
    bf16 *wouth, *woutl, *w1h, *w1l, *w2h, *w2l;
    float *z, *xln, *y2, *xT;
    cudaGetSymbolAddress((void**)&yh,  g_yh);
    cudaGetSymbolAddress((void**)&yl,  g_yl);
    cudaGetSymbolAddress((void**)&z,   g_z);
    cudaGetSymbolAddress((void**)&xln, g_xln);
    cudaGetSymbolAddress((void**)&xh,  g_xh);
    cudaGetSymbolAddress((void**)&xl,  g_xl);
    cudaGetSymbolAddress((void**)&y1h, g_y1h);
    cudaGetSymbolAddress((void**)&y1l, g_y1l);
    cudaGetSymbolAddress((void**)&y2,  g_y2);
    cudaGetSymbolAddress((void**)&xT,  g_xT);
    cudaGetSymbolAddress((void**)&wouth, g_wouth);
    cudaGetSymbolAddress((void**)&woutl, g_woutl);
    cudaGetSymbolAddress((void**)&w1h, g_w1h);
    cudaGetSymbolAddress((void**)&w1l, g_w1l);
    cudaGetSymbolAddress((void**)&w2h, g_w2h);
    cudaGetSymbolAddress((void**)&w2l, g_w2l);

    cudaFuncSetAttribute(gemm_mma, cudaFuncAttributeMaxDynamicSharedMemorySize, GEMM_SMEM);

    precompute_kernel<<<HDIM, NST>>>(log_dt, A_re, A_im, C_re, C_im);

    // transpose x -> (B,H,L) for coalesced scan loads
    transpose_kernel<<<dim3(LSEQ / 32, HDIM / 32, BSZ), 256>>>(x, xT);

    scan_part1<<<(BSZ * HDIM * (SEG - 1)) / 32, 256>>>(xT);
    scan_combine<<<(BSZ * HDIM * NST) / 256, 256>>>();
    scan_part2<<<(BSZ * HDIM * SEG) / 32, 256>>>(xT, D_skip, yh, yl);

    split_all_kernel<<<(4 * HDIM * HDIM + 255) / 256, 256>>>(W_out, W1, W2);

    gemm_mma<<<dim3((2 * HDIM) / 128, ROWS / 128), 256, GEMM_SMEM>>>(
        yh, yl, wouth, woutl, b_out, z, nullptr, nullptr, HDIM, 2 * HDIM, 0);

    glu_ln_kernel<<<ROWS, 128>>>(z, x, g1, beta1, xln, xh, xl);

    gemm_mma<<<dim3(HDIM / 128, ROWS / 128), 256, GEMM_SMEM>>>(
        xh, xl, w1h, w1l, bc1, nullptr, y1h, y1l, HDIM, HDIM, 1);

    gemm_mma<<<dim3(HDIM / 128, ROWS / 128), 256, GEMM_SMEM>>>(
        y1h, y1l, w2h, w2l, bc2, y2, nullptr, nullptr, HDIM, HDIM, 0);

    final_ln_kernel<<<ROWS, 128>>>(xln, y2, g2, beta2, out);
}

// round 11
// speedup vs baseline: 1.3061x; 1.2674x over previous
#include <cuda_runtime.h>
#include <cuda_bf16.h>
#include <cuda_fp16.h>
#include <math.h>
#include <stdint.h>

#define BSZ   8
#define LSEQ  2048
#define HDIM  512
#define NST   64
#define ROWS  (BSZ*LSEQ)      // 16384
#define SEG   16
#define SEGT  (LSEQ/SEG)      // 128

typedef __half fp16;
typedef __half2 fp162;

// ---------------- scratch ----------------------------------------------------------
__device__ float g_wre[HDIM*NST];
__device__ float g_wim[HDIM*NST];
__device__ float g_wTre[HDIM*NST];
__device__ float g_wTim[HDIM*NST];
__device__ float g_ctre[HDIM*NST];
__device__ float g_ctim[HDIM*NST];

__device__ float g_xT[(size_t)ROWS*HDIM];             // x transposed to (B, H, L)

__device__ float g_sendre[(size_t)BSZ*HDIM*SEG*NST];
__device__ float g_sendim[(size_t)BSZ*HDIM*SEG*NST];
__device__ float g_carre [(size_t)BSZ*HDIM*SEG*NST];
__device__ float g_carim [(size_t)BSZ*HDIM*SEG*NST];

__device__ fp16  g_yf [(size_t)ROWS*HDIM];   // S4 activation (fp16)
__device__ float g_z  [(size_t)ROWS*2*HDIM];
__device__ float g_xln[(size_t)ROWS*HDIM];
__device__ fp16  g_xf [(size_t)ROWS*HDIM];   // xln (fp16)
__device__ fp16  g_y1f[(size_t)ROWS*HDIM];   // FFN hidden (fp16)
__device__ float g_y2 [(size_t)ROWS*HDIM];

__device__ fp16 g_wouth[2*HDIM*HDIM];
__device__ fp16 g_woutl[2*HDIM*HDIM];
__device__ fp16 g_w1h[HDIM*HDIM];
__device__ fp16 g_w1l[HDIM*HDIM];
__device__ fp16 g_w2h[HDIM*HDIM];
__device__ fp16 g_w2l[HDIM*HDIM];

// =============================== helpers =========================================
__device__ __forceinline__ uint32_t smem_u32(const void* p) {
    uint32_t a;
    asm("{ .reg .u64 t; cvta.to.shared.u64 t, %1; cvt.u32.u64 %0, t; }" : "=r"(a) : "l"(p));
    return a;
}

__device__ __forceinline__ void ldmatrix_x4(uint32_t* r, uint32_t addr) {
    asm volatile("ldmatrix.sync.aligned.m8n8.x4.shared.b16 {%0,%1,%2,%3}, [%4];"
        : "=r"(r[0]), "=r"(r[1]), "=r"(r[2]), "=r"(r[3]) : "r"(addr));
}

__device__ __forceinline__ void mma_f16(float* c, const uint32_t* a,
                                        uint32_t b0, uint32_t b1) {
    asm volatile("mma.sync.aligned.m16n8k16.row.col.f32.f16.f16.f32 "
        "{%0,%1,%2,%3}, {%4,%5,%6,%7}, {%8,%9}, {%0,%1,%2,%3};"
        : "+f"(c[0]), "+f"(c[1]), "+f"(c[2]), "+f"(c[3])
        : "r"(a[0]), "r"(a[1]), "r"(a[2]), "r"(a[3]), "r"(b0), "r"(b1));
}

#define CP_ASYNC16(saddr, gaddr) \
    asm volatile("cp.async.cg.shared.global [%0], [%1], 16;" \
                 :: "r"(saddr), "l"(gaddr) : "memory")
#define CP_COMMIT() asm volatile("cp.async.commit_group;" ::: "memory")
#define CP_WAIT(n)  asm volatile("cp.async.wait_group %0;" :: "n"(n) : "memory")

// fp16 weight split: w = wh + wl (wl captures next ~11+ bits, may be subnormal — fine)
__device__ __forceinline__ void splitw(float v, fp16& h, fp16& l) {
    h = __float2half_rn(v);
    l = __float2half_rn(v - __half2float(h));
}

// ---- packed f32x2 ops (Blackwell) ----
__device__ __forceinline__ uint64_t pk2(float lo, float hi) {
    uint64_t r; asm("mov.b64 %0, {%1,%2};" : "=l"(r) : "f"(lo), "f"(hi)); return r;
}
__device__ __forceinline__ void upk2(uint64_t v, float& lo, float& hi) {
    asm("mov.b64 {%0,%1}, %2;" : "=f"(lo), "=f"(hi) : "l"(v));
}
__device__ __forceinline__ uint64_t fma2(uint64_t a, uint64_t b, uint64_t c) {
    uint64_t d; asm("fma.rn.f32x2 %0, %1, %2, %3;" : "=l"(d) : "l"(a), "l"(b), "l"(c)); return d;
}
__device__ __forceinline__ uint64_t mul2(uint64_t a, uint64_t b) {
    uint64_t d; asm("mul.rn.f32x2 %0, %1, %2;" : "=l"(d) : "l"(a), "l"(b)); return d;
}
__device__ __forceinline__ uint64_t add2(uint64_t a, uint64_t b) {
    uint64_t d; asm("add.rn.f32x2 %0, %1, %2;" : "=l"(d) : "l"(a), "l"(b)); return d;
}

// ---------------- x transpose: (B,L,H) -> (B,H,L) ---------------------------------
__global__ __launch_bounds__(256) void transpose_kernel(const float* __restrict__ x,
                                                        float* __restrict__ xT) {
    __shared__ float tile[32][33];
    int b  = blockIdx.z;
    int l0 = blockIdx.x * 32, h0 = blockIdx.y * 32;
    int tx = threadIdx.x & 31, ty = threadIdx.x >> 5;
    const float* xp = x + (size_t)b * LSEQ * HDIM;
#pragma unroll
    for (int i = 0; i < 32; i += 8)
        tile[ty + i][tx] = xp[(size_t)(l0 + ty + i) * HDIM + h0 + tx];
    __syncthreads();
    float* op = xT + (size_t)b * HDIM * LSEQ;
#pragma unroll
    for (int i = 0; i < 32; i += 8)
        op[(size_t)(h0 + ty + i) * LSEQ + l0 + tx] = tile[tx][ty + i];
}

// ---------------- weight split -----------------------------------------------------
__global__ void split_all_kernel(const float* __restrict__ wout,
                                 const float* __restrict__ w1,
                                 const float* __restrict__ w2) {
    int i = blockIdx.x * blockDim.x + threadIdx.x;
    const int n1 = 2 * HDIM * HDIM;
    const int n2 = HDIM * HDIM;
    if (i < n1) {
        fp16 h, l; splitw(wout[i], h, l);
        g_wouth[i] = h; g_woutl[i] = l;
    } else if (i < n1 + n2) {
        int j = i - n1;
        fp16 h, l; splitw(w1[j], h, l);
        g_w1h[j] = h; g_w1l[j] = l;
    } else {
        int j = i - n1 - n2;
        fp16 h, l; splitw(w2[j], h, l);
        g_w2h[j] = h; g_w2l[j] = l;
    }
}

// ---------------- precompute -------------------------------------------------------
__global__ void precompute_kernel(const float* __restrict__ log_dt,
                                  const float* __restrict__ Are,
                                  const float* __restrict__ Aim,
                                  const float* __restrict__ Cre,
                                  const float* __restrict__ Cim) {
    int h = blockIdx.x, n = threadIdx.x;
    int idx = h * NST + n;
    float dt = expf(log_dt[h]);
    float ar = Are[idx] * dt;
    float ai = Aim[idx] * dt;
    float e  = expf(ar);
    float sb, cb;
    sincosf(ai, &sb, &cb);
    float wre = e * cb, wim = e * sb;
    float eT = expf(ar * (float)SEGT);
    float sT, cT;
    sincosf(ai * (float)SEGT, &sT, &cT);
    g_wTre[idx] = eT * cT;
    g_wTim[idx] = eT * sT;

    float Ere = wre - 1.0f, Eim = wim;
    float Ar = Are[idx], Ai = Aim[idx];
    float inv = 1.0f / (Ar * Ar + Ai * Ai);
    float rre = (Ere * Ar + Eim * Ai) * inv;
    float rim = (Eim * Ar - Ere * Ai) * inv;
    float cr = Cre[idx], ci = Cim[idx];
    g_ctre[idx] = cr * rre - ci * rim;
    g_ctim[idx] = cr * rim + ci * rre;
    g_wre[idx]  = wre;
    g_wim[idx]  = wim;
}

// ---------------- scan pass 1 (coalesced u loads from xT) --------------------------
__global__ __launch_bounds__(256) void scan_part1(const float* __restrict__ xT) {
    int tid  = threadIdx.x;
    int gid  = blockIdx.x * 32 + (tid >> 3);
    int lane = tid & 7;
    int seg  = gid % (SEG - 1);
    int rem  = gid / (SEG - 1);
    int h = rem & (HDIM - 1);
    int b = rem >> 9;

    uint64_t wre01[4], wim01[4], nwim01[4], sre01[4], sim01[4];
    int base = h * NST + lane * 8;
#pragma unroll
    for (int p = 0; p < 4; p++) {
        float w0 = g_wre[base + 2*p], w1 = g_wre[base + 2*p + 1];
        float i0 = g_wim[base + 2*p], i1 = g_wim[base + 2*p + 1];
        wre01[p]  = pk2(w0, w1);
        wim01[p]  = pk2(i0, i1);
        nwim01[p] = pk2(-i0, -i1);
        sre01[p] = 0; sim01[p] = 0;
    }
    const float* xp = xT + ((size_t)(b * HDIM + h)) * LSEQ + seg * SEGT;

    float ucur = __ldg(xp + lane);
    for (int l0 = 0; l0 < SEGT; l0 += 8) {
        int ln = l0 + 8 + lane; if (ln > SEGT - 1) ln = SEGT - 1;
        float unext = __ldg(xp + ln);

        float ub[8];
#pragma unroll
        for (int k = 0; k < 8; k++) ub[k] = __shfl_sync(0xffffffffu, ucur, k, 8);

#pragma unroll
        for (int k = 0; k < 8; k++) {
            uint64_t u2 = pk2(ub[k], ub[k]);
#pragma unroll
            for (int p = 0; p < 4; p++) {
                uint64_t nr = fma2(wre01[p], sre01[p], fma2(nwim01[p], sim01[p], u2));
                uint64_t ni = fma2(wim01[p], sre01[p], mul2(wre01[p], sim01[p]));
                sre01[p] = nr; sim01[p] = ni;
            }
        }
        ucur = unext;
    }

    size_t ob = (((size_t)(b * HDIM + h) * SEG) + seg) * NST + lane * 8;
#pragma unroll
    for (int p = 0; p < 4; p++) {
        float r0, r1, i0, i1;
        upk2(sre01[p], r0, r1);
        upk2(sim01[p], i0, i1);
        g_sendre[ob + 2*p] = r0; g_sendre[ob + 2*p + 1] = r1;
        g_sendim[ob + 2*p] = i0; g_sendim[ob + 2*p + 1] = i1;
    }
}

// ---------------- combine ----------------------------------------------------------
__global__ __launch_bounds__(256) void scan_combine() {
    int idx = blockIdx.x * blockDim.x + threadIdx.x;
    int n = idx & (NST - 1);
    int rem = idx >> 6;
    int h = rem & (HDIM - 1);
    int b = rem >> 9;
    float wTre = g_wTre[h * NST + n];
    float wTim = g_wTim[h * NST + n];
    float cr = 0.0f, ci = 0.0f;
    size_t base = ((size_t)(b * HDIM + h) * SEG) * NST + n;
#pragma unroll
    for (int j = 0; j < SEG; j++) {
        g_carre[base + (size_t)j * NST] = cr;
        g_carim[base + (size_t)j * NST] = ci;
        if (j < SEG - 1) {
            float er = g_sendre[base + (size_t)j * NST];
            float ei = g_sendim[base + (size_t)j * NST];
            float nr = fmaf(wTre, cr, fmaf(-wTim, ci, er));
            float ni = fmaf(wTim, cr, fmaf(wTre, ci, ei));
            cr = nr; ci = ni;
        }
    }
}

// ---------------- scan pass 2 (single fp16 output) ---------------------------------
__global__ __launch_bounds__(256) void scan_part2(const float* __restrict__ xT,
                                                  const float* __restrict__ Dskip,
                                                  fp16* __restrict__ yf) {
    int tid  = threadIdx.x;
    int gid  = blockIdx.x * 32 + (tid >> 3);
    int lane = tid & 7;
    int seg  = gid & (SEG - 1);
    int rem  = gid >> 4;
    int h = rem & (HDIM - 1);
    int b = rem >> 9;

    uint64_t wre01[4], wim01[4], nwim01[4], cre01[4], ncim01[4], sre01[4], sim01[4];
    int base = h * NST + lane * 8;
    size_t cb = (((size_t)(b * HDIM + h) * SEG) + seg) * NST + lane * 8;
#pragma unroll
    for (int p = 0; p < 4; p++) {
        float w0 = g_wre[base + 2*p], w1 = g_wre[base + 2*p + 1];
        float i0 = g_wim[base + 2*p], i1 = g_wim[base + 2*p + 1];
        float c0 = g_ctre[base + 2*p], c1 = g_ctre[base + 2*p + 1];
        float d0 = g_ctim[base + 2*p], d1 = g_ctim[base + 2*p + 1];
        wre01[p]  = pk2(w0, w1);
        wim01[p]  = pk2(i0, i1);
        nwim01[p] = pk2(-i0, -i1);
        cre01[p]  = pk2(c0, c1);
        ncim01[p] = pk2(-d0, -d1);
        sre01[p] = pk2(g_carre[cb + 2*p], g_carre[cb + 2*p + 1]);
        sim01[p] = pk2(g_carim[cb + 2*p], g_carim[cb + 2*p + 1]);
    }
    float Dv = Dskip[h];
    const float* xp = xT + ((size_t)(b * HDIM + h)) * LSEQ + seg * SEGT;
    size_t orow = ((size_t)b * LSEQ + seg * SEGT) * HDIM + h;

    bool l1 = (lane & 1), l2 = (lane & 2), l4 = (lane & 4);

    float ucur = __ldg(xp + lane);
    for (int l0 = 0; l0 < SEGT; l0 += 8) {
        int ln = l0 + 8 + lane; if (ln > SEGT - 1) ln = SEGT - 1;
        float unext = __ldg(xp + ln);

        float buf[8];
#pragma unroll
        for (int k = 0; k < 8; k++) buf[k] = __shfl_sync(0xffffffffu, ucur, k, 8);

#pragma unroll
        for (int k = 0; k < 8; k++) {
            uint64_t u2 = pk2(buf[k], buf[k]);
            uint64_t accR, accI;
            {
                uint64_t nr = fma2(wre01[0], sre01[0], fma2(nwim01[0], sim01[0], u2));
                uint64_t ni = fma2(wim01[0], sre01[0], mul2(wre01[0], sim01[0]));
                sre01[0] = nr; sim01[0] = ni;
                accR = mul2(cre01[0], nr);
                accI = mul2(ncim01[0], ni);
            }
#pragma unroll
            for (int p = 1; p < 4; p++) {
                uint64_t nr = fma2(wre01[p], sre01[p], fma2(nwim01[p], sim01[p], u2));
                uint64_t ni = fma2(wim01[p], sre01[p], mul2(wre01[p], sim01[p]));
                sre01[p] = nr; sim01[p] = ni;
                accR = fma2(cre01[p], nr, accR);
                accI = fma2(ncim01[p], ni, accI);
            }
            uint64_t t = add2(accR, accI);
            float ta, tb; upk2(t, ta, tb);
            buf[k] = ta + tb;
        }

        float q[4], r[2], sfin;
#pragma unroll
        for (int j = 0; j < 4; j++) {
            float a = buf[2*j], bb = buf[2*j + 1];
            float sendv = l1 ? a : bb;
            float keepv = l1 ? bb : a;
            q[j] = keepv + __shfl_xor_sync(0xffffffffu, sendv, 1, 8);
        }
#pragma unroll
        for (int j = 0; j < 2; j++) {
            float a = q[2*j], bb = q[2*j + 1];
            float sendv = l2 ? a : bb;
            float keepv = l2 ? bb : a;
            r[j] = keepv + __shfl_xor_sync(0xffffffffu, sendv, 2, 8);
        }
        {
            float sendv = l4 ? r[0] : r[1];
            float keepv = l4 ? r[1] : r[0];
            sfin = keepv + __shfl_xor_sync(0xffffffffu, sendv, 4, 8);
        }

        float vv = fmaf(2.0f, sfin, Dv * ucur);
        float c = 0.7978845608028654f * (vv + 0.044715f * vv * vv * vv);
        float gv = vv / (1.0f + __expf(-2.0f * c));
        yf[orow + (size_t)(l0 + lane) * HDIM] = __float2half_rn(gv);

        ucur = unext;
    }
}

// ============ mma.sync 2-term fp16 GEMM: C = A_f16 @ (Bh+Bl)^T + bias ==============
#define LDSB   80
#define TILEB  (128 * LDSB)
#define STAGEB (3 * TILEB)          // A, Bh, Bl
#define NSTAGE 2
#define GEMM_SMEM (NSTAGE * STAGEB) // 61440 bytes

__global__ void __launch_bounds__(256, 2)
gemm_mma(const fp16* __restrict__ A,
         const fp16* __restrict__ Bh, const fp16* __restrict__ Bl,
         const float* __restrict__ bias,
         float* __restrict__ C, fp16* __restrict__ Cf,
         int K, int N, int mode) {   // mode 0: fp32 out; 1: relu + fp16 out
    extern __shared__ char smem[];
    uint32_t sbase = smem_u32(smem);
    int tid = threadIdx.x, wid = tid >> 5, lane = tid & 31;
    int row0 = blockIdx.y * 128, col0 = blockIdx.x * 128;
    int wm = wid >> 1, wn = wid & 1;

    float acc[2][8][4];
#pragma unroll
    for (int i = 0; i < 2; i++)
#pragma unroll
        for (int j = 0; j < 8; j++)
#pragma unroll
            for (int q = 0; q < 4; q++) acc[i][j][q] = 0.0f;

    int lr = tid >> 1;
    int lc = (tid & 1) * 16;
    const fp16* ap  = A  + (size_t)(row0 + lr) * K + lc;
    const fp16* bph = Bh + (size_t)(col0 + lr) * K + lc;
    const fp16* bpl = Bl + (size_t)(col0 + lr) * K + lc;
    uint32_t soff = (uint32_t)(lr * LDSB + lc * 2);

    int nch = K / 32;

    auto issue = [&](int c, int s) {
        uint32_t st = sbase + (uint32_t)s * STAGEB;
        int go = c * 32;
        uint32_t aa = st + soff;
        CP_ASYNC16(aa,      ap + go);
        CP_ASYNC16(aa + 16, ap + go + 8);
        uint32_t bh = st + TILEB + soff;
        CP_ASYNC16(bh,      bph + go);
        CP_ASYNC16(bh + 16, bph + go + 8);
        uint32_t bl = st + 2 * TILEB + soff;
        CP_ASYNC16(bl,      bpl + go);
        CP_ASYNC16(bl + 16, bpl + go + 8);
    };

    issue(0, 0);
    CP_COMMIT();

    int r_lm = (lane & 7) + ((lane >> 3) & 1) * 8;
    int k_lm = ((lane >> 4) & 1) * 8;

    for (int c = 0; c < nch; ++c) {
        CP_WAIT(0);
        __syncthreads();
        if (c + 1 < nch) {
            issue(c + 1, (c + 1) & 1);
            CP_COMMIT();
        }

        uint32_t st = sbase + (uint32_t)(c & 1) * STAGEB;

#pragma unroll
        for (int ks = 0; ks < 2; ++ks) {
            int kcol = ks * 16 + k_lm;
            uint32_t af[2][4];
#pragma unroll
            for (int mi = 0; mi < 2; ++mi) {
                int m = wm * 32 + mi * 16 + r_lm;
                ldmatrix_x4(af[mi], st + (uint32_t)(m * LDSB + kcol * 2));
            }
#pragma unroll
            for (int nj = 0; nj < 4; ++nj) {
                uint32_t bfh[4], bfl[4];
                int n = wn * 64 + nj * 16 + r_lm;
                uint32_t bd = st + TILEB + (uint32_t)(n * LDSB + kcol * 2);
                ldmatrix_x4(bfh, bd);
                ldmatrix_x4(bfl, bd + TILEB);
#pragma unroll
                for (int mi = 0; mi < 2; ++mi)
#pragma unroll
                    for (int h = 0; h < 2; ++h) {
                        float* cc = acc[mi][nj * 2 + h];
                        mma_f16(cc, af[mi], bfh[h], bfh[2 + h]);
                        mma_f16(cc, af[mi], bfl[h], bfl[2 + h]);
                    }
            }
        }
    }

    int tg = lane >> 2, tq = lane & 3;
#pragma unroll
    for (int mi = 0; mi < 2; ++mi) {
        int r = row0 + wm * 32 + mi * 16 + tg;
#pragma unroll
        for (int ni = 0; ni < 8; ++ni) {
            int cix = col0 + wn * 64 + ni * 8 + tq * 2;
            float b0 = bias[cix], b1 = bias[cix + 1];
            float v0 = acc[mi][ni][0] + b0, v1 = acc[mi][ni][1] + b1;
            float v2 = acc[mi][ni][2] + b0, v3 = acc[mi][ni][3] + b1;
            if (mode == 0) {
                *(float2*)(C + (size_t)r * N + cix) = make_float2(v0, v1);
                *(float2*)(C + (size_t)(r + 8) * N + cix) = make_float2(v2, v3);
            } else {
                v0 = fmaxf(v0, 0.0f); v1 = fmaxf(v1, 0.0f);
                v2 = fmaxf(v2, 0.0f); v3 = fmaxf(v3, 0.0f);
                *(fp162*)(Cf + (size_t)r * N + cix) =
                    __floats2half2_rn(v0, v1);
                *(fp162*)(Cf + (size_t)(r + 8) * N + cix) =
                    __floats2half2_rn(v2, v3);
            }
        }
    }
}

// ---------------- block reduce helper ---------------------------------------------
__device__ __forceinline__ float2 block_reduce_2(float a, float b) {
    unsigned m = 0xffffffffu;
#pragma unroll
    for (int o = 16; o > 0; o >>= 1) {
        a += __shfl_down_sync(m, a, o);
        b += __shfl_down_sync(m, b, o);
    }
    __shared__ float sa[4], sb[4];
    int w = threadIdx.x >> 5, lane = threadIdx.x & 31;
    if (lane == 0) { sa[w] = a; sb[w] = b; }
    __syncthreads();
    if (threadIdx.x == 0) {
        float ta = sa[0] + sa[1] + sa[2] + sa[3];
        float tb = sb[0] + sb[1] + sb[2] + sb[3];
        sa[0] = ta; sb[0] = tb;
    }
    __syncthreads();
    return make_float2(sa[0], sb[0]);
}

// ---------------- GLU + residual + LN1 (fp32 + fp16 out) ---------------------------
__global__ __launch_bounds__(128) void glu_ln_kernel(const float* __restrict__ z,
                                                     const float* __restrict__ x,
                                                     const float* __restrict__ g1,
                                                     const float* __restrict__ b1,
                                                     float* __restrict__ xln,
                                                     fp16* __restrict__ xf) {
    int row = blockIdx.x, tid = threadIdx.x;
    const float4* zr = (const float4*)(z + (size_t)row * (2 * HDIM));
    const float4* xr = (const float4*)(x + (size_t)row * HDIM);
    float4 a = zr[tid];
    float4 g = zr[tid + 128];
    float4 xv = xr[tid];
    float4 v;
    v.x = xv.x + a.x / (1.0f + __expf(-g.x));
    v.y = xv.y + a.y / (1.0f + __expf(-g.y));
    v.z = xv.z + a.z / (1.0f + __expf(-g.z));
    v.w = xv.w + a.w / (1.0f + __expf(-g.w));
    float s  = v.x + v.y + v.z + v.w;
    float s2 = v.x*v.x + v.y*v.y + v.z*v.z + v.w*v.w;
    float2 tot = block_reduce_2(s, s2);
    float mu = tot.x * (1.0f / HDIM);
    float var = tot.y * (1.0f / HDIM) - mu * mu;
    float rstd = rsqrtf(var + 1e-5f);
    float4 gv = ((const float4*)g1)[tid];
    float4 bv = ((const float4*)b1)[tid];
    float4 o;
    o.x = (v.x - mu) * rstd * gv.x + bv.x;
    o.y = (v.y - mu) * rstd * gv.y + bv.y;
    o.z = (v.z - mu) * rstd * gv.z + bv.z;
    o.w = (v.w - mu) * rstd * gv.w + bv.w;
    ((float4*)(xln + (size_t)row * HDIM))[tid] = o;
    fp162* xf2 = (fp162*)(xf + (size_t)row * HDIM);
    xf2[tid*2]   = __floats2half2_rn(o.x, o.y);
    xf2[tid*2+1] = __floats2half2_rn(o.z, o.w);
}

// ---------------- residual + LN2 (float4) -------------------------------------------
__global__ __launch_bounds__(128) void final_ln_kernel(const float* __restrict__ xln,
                                                       const float* __restrict__ y2,
                                                       const float* __restrict__ g2,
                                                       const float* __restrict__ b2,
                                                       float* __restrict__ out) {
    int row = blockIdx.x, tid = threadIdx.x;
    float4 a = ((const float4*)(xln + (size_t)row * HDIM))[tid];
    float4 b = ((const float4*)(y2  + (size_t)row * HDIM))[tid];
    float4 v;
    v.x = a.x + b.x; v.y = a.y + b.y; v.z = a.z + b.z; v.w = a.w + b.w;
    float s  = v.x + v.y + v.z + v.w;
    float s2 = v.x*v.x + v.y*v.y + v.z*v.z + v.w*v.w;
    float2 tot = block_reduce_2(s, s2);
    float mu = tot.x * (1.0f / HDIM);
    float var = tot.y * (1.0f / HDIM) - mu * mu;
    float rstd = rsqrtf(var + 1e-5f);
    float4 gv = ((const float4*)g2)[tid];
    float4 bv = ((const float4*)b2)[tid];
    float4 o;
    o.x = (v.x - mu) * rstd * gv.x + bv.x;
    o.y = (v.y - mu) * rstd * gv.y + bv.y;
    o.z = (v.z - mu) * rstd * gv.z + bv.z;
    o.w = (v.w - mu) * rstd * gv.w + bv.w;
    ((float4*)(out + (size_t)row * HDIM))[tid] = o;
}

// ---------------- launch ------------------------------------------------------------
extern "C" void kernel_launch(void* const* d_in, const int* in_sizes, int n_in,
                              void* d_out, int out_size) {
    const float* x      = (const float*)d_in[0];
    const float* log_dt = (const float*)d_in[1];
    const float* A_re   = (const float*)d_in[2];
    const float* A_im   = (const float*)d_in[3];
    const float* C_re   = (const float*)d_in[4];
    const float* C_im   = (const float*)d_in[5];
    const float* D_skip = (const float*)d_in[6];
    const float* W_out  = (const float*)d_in[7];
    const float* b_out  = (const float*)d_in[8];
    const float* g1     = (const float*)d_in[9];
    const float* beta1  = (const float*)d_in[10];
    const float* g2     = (const float*)d_in[11];
    const float* beta2  = (const float*)d_in[12];
    const float* W1     = (const float*)d_in[13];
    const float* bc1    = (const float*)d_in[14];
    const float* W2     = (const float*)d_in[15];
    const float* bc2    = (const float*)d_in[16];
    float* out = (float*)d_out;

    fp16 *yf, *xf, *y1f;
    fp16 *wouth, *woutl, *w1h, *w1l, *w2h, *w2l;
    float *z, *xln, *y2, *xT;
    cudaGetSymbolAddress((void**)&yf,  g_yf);
    cudaGetSymbolAddress((void**)&z,   g_z);
    cudaGetSymbolAddress((void**)&xln, g_xln);
    cudaGetSymbolAddress((void**)&xf,  g_xf);
    cudaGetSymbolAddress((void**)&y1f, g_y1f);
    cudaGetSymbolAddress((void**)&y2,  g_y2);
    cudaGetSymbolAddress((void**)&xT,  g_xT);
    cudaGetSymbolAddress((void**)&wouth, g_wouth);
    cudaGetSymbolAddress((void**)&woutl, g_woutl);
    cudaGetSymbolAddress((void**)&w1h, g_w1h);
    cudaGetSymbolAddress((void**)&w1l, g_w1l);
    cudaGetSymbolAddress((void**)&w2h, g_w2h);
    cudaGetSymbolAddress((void**)&w2l, g_w2l);

    cudaFuncSetAttribute(gemm_mma, cudaFuncAttributeMaxDynamicSharedMemorySize, GEMM_SMEM);

    precompute_kernel<<<HDIM, NST>>>(log_dt, A_re, A_im, C_re, C_im);
    transpose_kernel<<<dim3(LSEQ / 32, HDIM / 32, BSZ), 256>>>(x, xT);

    scan_part1<<<(BSZ * HDIM * (SEG - 1)) / 32, 256>>>(xT);
    scan_combine<<<(BSZ * HDIM * NST) / 256, 256>>>();
    scan_part2<<<(BSZ * HDIM * SEG) / 32, 256>>>(xT, D_skip, yf);

    split_all_kernel<<<(4 * HDIM * HDIM + 255) / 256, 256>>>(W_out, W1, W2);

    gemm_mma<<<dim3((2 * HDIM) / 128, ROWS / 128), 256, GEMM_SMEM>>>(
        yf, wouth, woutl, b_out, z, nullptr, HDIM, 2 * HDIM, 0);

    glu_ln_kernel<<<ROWS, 128>>>(z, x, g1, beta1, xln, xf);

    gemm_mma<<<dim3(HDIM / 128, ROWS / 128), 256, GEMM_SMEM>>>(
        xf, w1h, w1l, bc1, nullptr, y1f, HDIM, HDIM, 1);

    gemm_mma<<<dim3(HDIM / 128, ROWS / 128), 256, GEMM_SMEM>>>(
        y1f, w2h, w2l, bc2, y2, nullptr, HDIM, HDIM, 0);

    final_ln_kernel<<<ROWS, 128>>>(xln, y2, g2, beta2, out);
}

// round 12
// speedup vs baseline: 1.5876x; 1.2156x over previous
#include <cuda_runtime.h>
#include <cuda_bf16.h>
#include <cuda_fp16.h>
#include <math.h>
#include <stdint.h>

#define BSZ   8
#define LSEQ  2048
#define HDIM  512
#define NST   64
#define ROWS  (BSZ*LSEQ)      // 16384
#define SEG   16
#define SEGT  (LSEQ/SEG)      // 128

typedef __half fp16;
typedef __half2 fp162;

// ---------------- scratch ----------------------------------------------------------
__device__ float g_wre[HDIM*NST];
__device__ float g_wim[HDIM*NST];
__device__ float g_wTre[HDIM*NST];
__device__ float g_wTim[HDIM*NST];
__device__ float g_ctre[HDIM*NST];
__device__ float g_ctim[HDIM*NST];

__device__ float g_xT[(size_t)ROWS*HDIM];             // x transposed to (B, H, L)

__device__ float g_sendre[(size_t)BSZ*HDIM*SEG*NST];
__device__ float g_sendim[(size_t)BSZ*HDIM*SEG*NST];
__device__ float g_carre [(size_t)BSZ*HDIM*SEG*NST];
__device__ float g_carim [(size_t)BSZ*HDIM*SEG*NST];

__device__ fp16  g_yf [(size_t)ROWS*HDIM];   // S4 activation (fp16)
__device__ float g_z  [(size_t)ROWS*2*HDIM];
__device__ float g_xln[(size_t)ROWS*HDIM];
__device__ fp16  g_xf [(size_t)ROWS*HDIM];   // xln (fp16)
__device__ fp16  g_y1f[(size_t)ROWS*HDIM];   // FFN hidden (fp16)
__device__ float g_y2 [(size_t)ROWS*HDIM];

__device__ fp16 g_woutf[2*HDIM*HDIM];
__device__ fp16 g_w1f[HDIM*HDIM];
__device__ fp16 g_w2f[HDIM*HDIM];

// =============================== helpers =========================================
__device__ __forceinline__ uint32_t smem_u32(const void* p) {
    uint32_t a;
    asm("{ .reg .u64 t; cvta.to.shared.u64 t, %1; cvt.u32.u64 %0, t; }" : "=r"(a) : "l"(p));
    return a;
}

__device__ __forceinline__ void ldmatrix_x4(uint32_t* r, uint32_t addr) {
    asm volatile("ldmatrix.sync.aligned.m8n8.x4.shared.b16 {%0,%1,%2,%3}, [%4];"
        : "=r"(r[0]), "=r"(r[1]), "=r"(r[2]), "=r"(r[3]) : "r"(addr));
}

__device__ __forceinline__ void mma_f16(float* c, const uint32_t* a,
                                        uint32_t b0, uint32_t b1) {
    asm volatile("mma.sync.aligned.m16n8k16.row.col.f32.f16.f16.f32 "
        "{%0,%1,%2,%3}, {%4,%5,%6,%7}, {%8,%9}, {%0,%1,%2,%3};"
        : "+f"(c[0]), "+f"(c[1]), "+f"(c[2]), "+f"(c[3])
        : "r"(a[0]), "r"(a[1]), "r"(a[2]), "r"(a[3]), "r"(b0), "r"(b1));
}

#define CP_ASYNC16(saddr, gaddr) \
    asm volatile("cp.async.cg.shared.global [%0], [%1], 16;" \
                 :: "r"(saddr), "l"(gaddr) : "memory")
#define CP_COMMIT() asm volatile("cp.async.commit_group;" ::: "memory")
#define CP_WAIT(n)  asm volatile("cp.async.wait_group %0;" :: "n"(n) : "memory")

// ---- packed f32x2 ops (Blackwell) ----
__device__ __forceinline__ uint64_t pk2(float lo, float hi) {
    uint64_t r; asm("mov.b64 %0, {%1,%2};" : "=l"(r) : "f"(lo), "f"(hi)); return r;
}
__device__ __forceinline__ void upk2(uint64_t v, float& lo, float& hi) {
    asm("mov.b64 {%0,%1}, %2;" : "=f"(lo), "=f"(hi) : "l"(v));
}
__device__ __forceinline__ uint64_t fma2(uint64_t a, uint64_t b, uint64_t c) {
    uint64_t d; asm("fma.rn.f32x2 %0, %1, %2, %3;" : "=l"(d) : "l"(a), "l"(b), "l"(c)); return d;
}
__device__ __forceinline__ uint64_t mul2(uint64_t a, uint64_t b) {
    uint64_t d; asm("mul.rn.f32x2 %0, %1, %2;" : "=l"(d) : "l"(a), "l"(b)); return d;
}
__device__ __forceinline__ uint64_t add2(uint64_t a, uint64_t b) {
    uint64_t d; asm("add.rn.f32x2 %0, %1, %2;" : "=l"(d) : "l"(a), "l"(b)); return d;
}

// ---------------- x transpose: (B,L,H) -> (B,H,L) ---------------------------------
__global__ __launch_bounds__(256) void transpose_kernel(const float* __restrict__ x,
                                                        float* __restrict__ xT) {
    __shared__ float tile[32][33];
    int b  = blockIdx.z;
    int l0 = blockIdx.x * 32, h0 = blockIdx.y * 32;
    int tx = threadIdx.x & 31, ty = threadIdx.x >> 5;
    const float* xp = x + (size_t)b * LSEQ * HDIM;
#pragma unroll
    for (int i = 0; i < 32; i += 8)
        tile[ty + i][tx] = xp[(size_t)(l0 + ty + i) * HDIM + h0 + tx];
    __syncthreads();
    float* op = xT + (size_t)b * HDIM * LSEQ;
#pragma unroll
    for (int i = 0; i < 32; i += 8)
        op[(size_t)(h0 + ty + i) * LSEQ + l0 + tx] = tile[tx][ty + i];
}

// ---------------- weight convert (fp32 -> fp16, all three) -------------------------
__global__ void convert_w_kernel(const float* __restrict__ wout,
                                 const float* __restrict__ w1,
                                 const float* __restrict__ w2) {
    int i = blockIdx.x * blockDim.x + threadIdx.x;
    const int n1 = 2 * HDIM * HDIM;
    const int n2 = HDIM * HDIM;
    if (i < n1) {
        g_woutf[i] = __float2half_rn(wout[i]);
    } else if (i < n1 + n2) {
        g_w1f[i - n1] = __float2half_rn(w1[i - n1]);
    } else {
        g_w2f[i - n1 - n2] = __float2half_rn(w2[i - n1 - n2]);
    }
}

// ---------------- precompute -------------------------------------------------------
__global__ void precompute_kernel(const float* __restrict__ log_dt,
                                  const float* __restrict__ Are,
                                  const float* __restrict__ Aim,
                                  const float* __restrict__ Cre,
                                  const float* __restrict__ Cim) {
    int h = blockIdx.x, n = threadIdx.x;
    int idx = h * NST + n;
    float dt = expf(log_dt[h]);
    float ar = Are[idx] * dt;
    float ai = Aim[idx] * dt;
    float e  = expf(ar);
    float sb, cb;
    sincosf(ai, &sb, &cb);
    float wre = e * cb, wim = e * sb;
    float eT = expf(ar * (float)SEGT);
    float sT, cT;
    sincosf(ai * (float)SEGT, &sT, &cT);
    g_wTre[idx] = eT * cT;
    g_wTim[idx] = eT * sT;

    float Ere = wre - 1.0f, Eim = wim;
    float Ar = Are[idx], Ai = Aim[idx];
    float inv = 1.0f / (Ar * Ar + Ai * Ai);
    float rre = (Ere * Ar + Eim * Ai) * inv;
    float rim = (Eim * Ar - Ere * Ai) * inv;
    float cr = Cre[idx], ci = Cim[idx];
    g_ctre[idx] = cr * rre - ci * rim;
    g_ctim[idx] = cr * rim + ci * rre;
    g_wre[idx]  = wre;
    g_wim[idx]  = wim;
}

// ---------------- scan pass 1: 16 lanes/group, 4 states/lane -----------------------
__global__ __launch_bounds__(256) void scan_part1(const float* __restrict__ xT) {
    int tid  = threadIdx.x;
    int gid  = blockIdx.x * 16 + (tid >> 4);
    int lane = tid & 15;
    int seg  = gid % (SEG - 1);
    int rem  = gid / (SEG - 1);
    int h = rem & (HDIM - 1);
    int b = rem >> 9;

    uint64_t wre01[2], wim01[2], nwim01[2], sre01[2], sim01[2];
    int base = h * NST + lane * 4;
#pragma unroll
    for (int p = 0; p < 2; p++) {
        float w0 = g_wre[base + 2*p], w1 = g_wre[base + 2*p + 1];
        float i0 = g_wim[base + 2*p], i1 = g_wim[base + 2*p + 1];
        wre01[p]  = pk2(w0, w1);
        wim01[p]  = pk2(i0, i1);
        nwim01[p] = pk2(-i0, -i1);
        sre01[p] = 0; sim01[p] = 0;
    }
    const float* xp = xT + ((size_t)(b * HDIM + h)) * LSEQ + seg * SEGT;

    float ucur = __ldg(xp + lane);
    for (int l0 = 0; l0 < SEGT; l0 += 16) {
        int ln = l0 + 16 + lane; if (ln > SEGT - 1) ln = SEGT - 1;
        float unext = __ldg(xp + ln);

        float ub[16];
#pragma unroll
        for (int k = 0; k < 16; k++) ub[k] = __shfl_sync(0xffffffffu, ucur, k, 16);

#pragma unroll
        for (int k = 0; k < 16; k++) {
            uint64_t u2 = pk2(ub[k], ub[k]);
#pragma unroll
            for (int p = 0; p < 2; p++) {
                uint64_t nr = fma2(wre01[p], sre01[p], fma2(nwim01[p], sim01[p], u2));
                uint64_t ni = fma2(wim01[p], sre01[p], mul2(wre01[p], sim01[p]));
                sre01[p] = nr; sim01[p] = ni;
            }
        }
        ucur = unext;
    }

    size_t ob = (((size_t)(b * HDIM + h) * SEG) + seg) * NST + lane * 4;
#pragma unroll
    for (int p = 0; p < 2; p++) {
        float r0, r1, i0, i1;
        upk2(sre01[p], r0, r1);
        upk2(sim01[p], i0, i1);
        g_sendre[ob + 2*p] = r0; g_sendre[ob + 2*p + 1] = r1;
        g_sendim[ob + 2*p] = i0; g_sendim[ob + 2*p + 1] = i1;
    }
}

// ---------------- combine ----------------------------------------------------------
__global__ __launch_bounds__(256) void scan_combine() {
    int idx = blockIdx.x * blockDim.x + threadIdx.x;
    int n = idx & (NST - 1);
    int rem = idx >> 6;
    int h = rem & (HDIM - 1);
    int b = rem >> 9;
    float wTre = g_wTre[h * NST + n];
    float wTim = g_wTim[h * NST + n];
    float cr = 0.0f, ci = 0.0f;
    size_t base = ((size_t)(b * HDIM + h) * SEG) * NST + n;
#pragma unroll
    for (int j = 0; j < SEG; j++) {
        g_carre[base + (size_t)j * NST] = cr;
        g_carim[base + (size_t)j * NST] = ci;
        if (j < SEG - 1) {
            float er = g_sendre[base + (size_t)j * NST];
            float ei = g_sendim[base + (size_t)j * NST];
            float nr = fmaf(wTre, cr, fmaf(-wTim, ci, er));
            float ni = fmaf(wTim, cr, fmaf(wTre, ci, ei));
            cr = nr; ci = ni;
        }
    }
}

// ---------------- scan pass 2: 16 lanes/group, 4 states/lane -----------------------
__global__ __launch_bounds__(256) void scan_part2(const float* __restrict__ xT,
                                                  const float* __restrict__ Dskip,
                                                  fp16* __restrict__ yf) {
    int tid  = threadIdx.x;
    int gid  = blockIdx.x * 16 + (tid >> 4);
    int lane = tid & 15;
    int seg  = gid & (SEG - 1);
    int rem  = gid >> 4;
    int h = rem & (HDIM - 1);
    int b = rem >> 9;

    uint64_t wre01[2], wim01[2], nwim01[2], cre01[2], ncim01[2], sre01[2], sim01[2];
    int base = h * NST + lane * 4;
    size_t cb = (((size_t)(b * HDIM + h) * SEG) + seg) * NST + lane * 4;
#pragma unroll
    for (int p = 0; p < 2; p++) {
        float w0 = g_wre[base + 2*p], w1 = g_wre[base + 2*p + 1];
        float i0 = g_wim[base + 2*p], i1 = g_wim[base + 2*p + 1];
        float c0 = g_ctre[base + 2*p], c1 = g_ctre[base + 2*p + 1];
        float d0 = g_ctim[base + 2*p], d1 = g_ctim[base + 2*p + 1];
        wre01[p]  = pk2(w0, w1);
        wim01[p]  = pk2(i0, i1);
        nwim01[p] = pk2(-i0, -i1);
        cre01[p]  = pk2(c0, c1);
        ncim01[p] = pk2(-d0, -d1);
        sre01[p] = pk2(g_carre[cb + 2*p], g_carre[cb + 2*p + 1]);
        sim01[p] = pk2(g_carim[cb + 2*p], g_carim[cb + 2*p + 1]);
    }
    float Dv = Dskip[h];
    const float* xp = xT + ((size_t)(b * HDIM + h)) * LSEQ + seg * SEGT;
    size_t orow = ((size_t)b * LSEQ + seg * SEGT) * HDIM + h;

    bool l1 = (lane & 1), l2 = (lane & 2), l4 = (lane & 4), l8 = (lane & 8);

    float ucur = __ldg(xp + lane);
    for (int l0 = 0; l0 < SEGT; l0 += 16) {
        int ln = l0 + 16 + lane; if (ln > SEGT - 1) ln = SEGT - 1;
        float unext = __ldg(xp + ln);

        float buf[16];
#pragma unroll
        for (int k = 0; k < 16; k++) buf[k] = __shfl_sync(0xffffffffu, ucur, k, 16);

#pragma unroll
        for (int k = 0; k < 16; k++) {
            uint64_t u2 = pk2(buf[k], buf[k]);
            uint64_t accR, accI;
            {
                uint64_t nr = fma2(wre01[0], sre01[0], fma2(nwim01[0], sim01[0], u2));
                uint64_t ni = fma2(wim01[0], sre01[0], mul2(wre01[0], sim01[0]));
                sre01[0] = nr; sim01[0] = ni;
                accR = mul2(cre01[0], nr);
                accI = mul2(ncim01[0], ni);
            }
            {
                uint64_t nr = fma2(wre01[1], sre01[1], fma2(nwim01[1], sim01[1], u2));
                uint64_t ni = fma2(wim01[1], sre01[1], mul2(wre01[1], sim01[1]));
                sre01[1] = nr; sim01[1] = ni;
                accR = fma2(cre01[1], nr, accR);
                accI = fma2(ncim01[1], ni, accI);
            }
            uint64_t t = add2(accR, accI);
            float ta, tb; upk2(t, ta, tb);
            buf[k] = ta + tb;
        }

        // 4-stage recursive-halving transpose reduce over 16 lanes
        float q8[8], q4[4], q2[2], sfin;
#pragma unroll
        for (int j = 0; j < 8; j++) {
            float a = buf[2*j], bb = buf[2*j + 1];
            float sendv = l1 ? a : bb;
            float keepv = l1 ? bb : a;
            q8[j] = keepv + __shfl_xor_sync(0xffffffffu, sendv, 1, 16);
        }
#pragma unroll
        for (int j = 0; j < 4; j++) {
            float a = q8[2*j], bb = q8[2*j + 1];
            float sendv = l2 ? a : bb;
            float keepv = l2 ? bb : a;
            q4[j] = keepv + __shfl_xor_sync(0xffffffffu, sendv, 2, 16);
        }
#pragma unroll
        for (int j = 0; j < 2; j++) {
            float a = q4[2*j], bb = q4[2*j + 1];
            float sendv = l4 ? a : bb;
            float keepv = l4 ? bb : a;
            q2[j] = keepv + __shfl_xor_sync(0xffffffffu, sendv, 4, 16);
        }
        {
            float sendv = l8 ? q2[0] : q2[1];
            float keepv = l8 ? q2[1] : q2[0];
            sfin = keepv + __shfl_xor_sync(0xffffffffu, sendv, 8, 16);
        }

        float vv = fmaf(2.0f, sfin, Dv * ucur);
        float c = 0.7978845608028654f * (vv + 0.044715f * vv * vv * vv);
        float gv = vv / (1.0f + __expf(-2.0f * c));
        yf[orow + (size_t)(l0 + lane) * HDIM] = __float2half_rn(gv);

        ucur = unext;
    }
}

// ============ mma.sync plain fp16 GEMM: C = A_f16 @ B_f16^T + bias =================
#define LDSB   80
#define TILEB  (128 * LDSB)
#define STAGEB (2 * TILEB)          // A, B
#define NSTAGE 2
#define GEMM_SMEM (NSTAGE * STAGEB) // 40960 bytes

__global__ void __launch_bounds__(256, 2)
gemm_mma(const fp16* __restrict__ A, const fp16* __restrict__ B,
         const float* __restrict__ bias,
         float* __restrict__ C, fp16* __restrict__ Cf,
         int K, int N, int mode) {   // mode 0: fp32 out; 1: relu + fp16 out
    extern __shared__ char smem[];
    uint32_t sbase = smem_u32(smem);
    int tid = threadIdx.x, wid = tid >> 5, lane = tid & 31;
    int row0 = blockIdx.y * 128, col0 = blockIdx.x * 128;
    int wm = wid >> 1, wn = wid & 1;

    float acc[2][8][4];
#pragma unroll
    for (int i = 0; i < 2; i++)
#pragma unroll
        for (int j = 0; j < 8; j++)
#pragma unroll
            for (int q = 0; q < 4; q++) acc[i][j][q] = 0.0f;

    int lr = tid >> 1;
    int lc = (tid & 1) * 16;
    const fp16* ap = A + (size_t)(row0 + lr) * K + lc;
    const fp16* bp = B + (size_t)(col0 + lr) * K + lc;
    uint32_t soff = (uint32_t)(lr * LDSB + lc * 2);

    int nch = K / 32;

    auto issue = [&](int c, int s) {
        uint32_t st = sbase + (uint32_t)s * STAGEB;
        int go = c * 32;
        uint32_t aa = st + soff;
        CP_ASYNC16(aa,      ap + go);
        CP_ASYNC16(aa + 16, ap + go + 8);
        uint32_t bb = st + TILEB + soff;
        CP_ASYNC16(bb,      bp + go);
        CP_ASYNC16(bb + 16, bp + go + 8);
    };

    issue(0, 0);
    CP_COMMIT();

    int r_lm = (lane & 7) + ((lane >> 3) & 1) * 8;
    int k_lm = ((lane >> 4) & 1) * 8;

    for (int c = 0; c < nch; ++c) {
        CP_WAIT(0);
        __syncthreads();
        if (c + 1 < nch) {
            issue(c + 1, (c + 1) & 1);
            CP_COMMIT();
        }

        uint32_t st = sbase + (uint32_t)(c & 1) * STAGEB;

#pragma unroll
        for (int ks = 0; ks < 2; ++ks) {
            int kcol = ks * 16 + k_lm;
            uint32_t af[2][4];
#pragma unroll
            for (int mi = 0; mi < 2; ++mi) {
                int m = wm * 32 + mi * 16 + r_lm;
                ldmatrix_x4(af[mi], st + (uint32_t)(m * LDSB + kcol * 2));
            }
#pragma unroll
            for (int nj = 0; nj < 4; ++nj) {
                uint32_t bf[4];
                int n = wn * 64 + nj * 16 + r_lm;
                ldmatrix_x4(bf, st + TILEB + (uint32_t)(n * LDSB + kcol * 2));
#pragma unroll
                for (int mi = 0; mi < 2; ++mi)
#pragma unroll
                    for (int h = 0; h < 2; ++h)
                        mma_f16(acc[mi][nj * 2 + h], af[mi], bf[h], bf[2 + h]);
            }
        }
    }

    int tg = lane >> 2, tq = lane & 3;
#pragma unroll
    for (int mi = 0; mi < 2; ++mi) {
        int r = row0 + wm * 32 + mi * 16 + tg;
#pragma unroll
        for (int ni = 0; ni < 8; ++ni) {
            int cix = col0 + wn * 64 + ni * 8 + tq * 2;
            float b0 = bias[cix], b1 = bias[cix + 1];
            float v0 = acc[mi][ni][0] + b0, v1 = acc[mi][ni][1] + b1;
            float v2 = acc[mi][ni][2] + b0, v3 = acc[mi][ni][3] + b1;
            if (mode == 0) {
                *(float2*)(C + (size_t)r * N + cix) = make_float2(v0, v1);
                *(float2*)(C + (size_t)(r + 8) * N + cix) = make_float2(v2, v3);
            } else {
                v0 = fmaxf(v0, 0.0f); v1 = fmaxf(v1, 0.0f);
                v2 = fmaxf(v2, 0.0f); v3 = fmaxf(v3, 0.0f);
                *(fp162*)(Cf + (size_t)r * N + cix) = __floats2half2_rn(v0, v1);
                *(fp162*)(Cf + (size_t)(r + 8) * N + cix) = __floats2half2_rn(v2, v3);
            }
        }
    }
}

// ---------------- block reduce helper ---------------------------------------------
__device__ __forceinline__ float2 block_reduce_2(float a, float b) {
    unsigned m = 0xffffffffu;
#pragma unroll
    for (int o = 16; o > 0; o >>= 1) {
        a += __shfl_down_sync(m, a, o);
        b += __shfl_down_sync(m, b, o);
    }
    __shared__ float sa[4], sb[4];
    int w = threadIdx.x >> 5, lane = threadIdx.x & 31;
    if (lane == 0) { sa[w] = a; sb[w] = b; }
    __syncthreads();
    if (threadIdx.x == 0) {
        float ta = sa[0] + sa[1] + sa[2] + sa[3];
        float tb = sb[0] + sb[1] + sb[2] + sb[3];
        sa[0] = ta; sb[0] = tb;
    }
    __syncthreads();
    return make_float2(sa[0], sb[0]);
}

// ---------------- GLU + residual + LN1 (fp32 + fp16 out) ---------------------------
__global__ __launch_bounds__(128) void glu_ln_kernel(const float* __restrict__ z,
                                                     const float* __restrict__ x,
                                                     const float* __restrict__ g1,
                                                     const float* __restrict__ b1,
                                                     float* __restrict__ xln,
                                                     fp16* __restrict__ xf) {
    int row = blockIdx.x, tid = threadIdx.x;
    const float4* zr = (const float4*)(z + (size_t)row * (2 * HDIM));
    const float4* xr = (const float4*)(x + (size_t)row * HDIM);
    float4 a = zr[tid];
    float4 g = zr[tid + 128];
    float4 xv = xr[tid];
    float4 v;
    v.x = xv.x + a.x / (1.0f + __expf(-g.x));
    v.y = xv.y + a.y / (1.0f + __expf(-g.y));
    v.z = xv.z + a.z / (1.0f + __expf(-g.z));
    v.w = xv.w + a.w / (1.0f + __expf(-g.w));
    float s  = v.x + v.y + v.z + v.w;
    float s2 = v.x*v.x + v.y*v.y + v.z*v.z + v.w*v.w;
    float2 tot = block_reduce_2(s, s2);
    float mu = tot.x * (1.0f / HDIM);
    float var = tot.y * (1.0f / HDIM) - mu * mu;
    float rstd = rsqrtf(var + 1e-5f);
    float4 gv = ((const float4*)g1)[tid];
    float4 bv = ((const float4*)b1)[tid];
    float4 o;
    o.x = (v.x - mu) * rstd * gv.x + bv.x;
    o.y = (v.y - mu) * rstd * gv.y + bv.y;
    o.z = (v.z - mu) * rstd * gv.z + bv.z;
    o.w = (v.w - mu) * rstd * gv.w + bv.w;
    ((float4*)(xln + (size_t)row * HDIM))[tid] = o;
    fp162* xf2 = (fp162*)(xf + (size_t)row * HDIM);
    xf2[tid*2]   = __floats2half2_rn(o.x, o.y);
    xf2[tid*2+1] = __floats2half2_rn(o.z, o.w);
}

// ---------------- residual + LN2 (float4) -------------------------------------------
__global__ __launch_bounds__(128) void final_ln_kernel(const float* __restrict__ xln,
                                                       const float* __restrict__ y2,
                                                       const float* __restrict__ g2,
                                                       const float* __restrict__ b2,
                                                       float* __restrict__ out) {
    int row = blockIdx.x, tid = threadIdx.x;
    float4 a = ((const float4*)(xln + (size_t)row * HDIM))[tid];
    float4 b = ((const float4*)(y2  + (size_t)row * HDIM))[tid];
    float4 v;
    v.x = a.x + b.x; v.y = a.y + b.y; v.z = a.z + b.z; v.w = a.w + b.w;
    float s  = v.x + v.y + v.z + v.w;
    float s2 = v.x*v.x + v.y*v.y + v.z*v.z + v.w*v.w;
    float2 tot = block_reduce_2(s, s2);
    float mu = tot.x * (1.0f / HDIM);
    float var = tot.y * (1.0f / HDIM) - mu * mu;
    float rstd = rsqrtf(var + 1e-5f);
    float4 gv = ((const float4*)g2)[tid];
    float4 bv = ((const float4*)b2)[tid];
    float4 o;
    o.x = (v.x - mu) * rstd * gv.x + bv.x;
    o.y = (v.y - mu) * rstd * gv.y + bv.y;
    o.z = (v.z - mu) * rstd * gv.z + bv.z;
    o.w = (v.w - mu) * rstd * gv.w + bv.w;
    ((float4*)(out + (size_t)row * HDIM))[tid] = o;
}

// ---------------- launch ------------------------------------------------------------
extern "C" void kernel_launch(void* const* d_in, const int* in_sizes, int n_in,
                              void* d_out, int out_size) {
    const float* x      = (const float*)d_in[0];
    const float* log_dt = (const float*)d_in[1];
    const float* A_re   = (const float*)d_in[2];
    const float* A_im   = (const float*)d_in[3];
    const float* C_re   = (const float*)d_in[4];
    const float* C_im   = (const float*)d_in[5];
    const float* D_skip = (const float*)d_in[6];
    const float* W_out  = (const float*)d_in[7];
    const float* b_out  = (const float*)d_in[8];
    const float* g1     = (const float*)d_in[9];
    const float* beta1  = (const float*)d_in[10];
    const float* g2     = (const float*)d_in[11];
    const float* beta2  = (const float*)d_in[12];
    const float* W1     = (const float*)d_in[13];
    const float* bc1    = (const float*)d_in[14];
    const float* W2     = (const float*)d_in[15];
    const float* bc2    = (const float*)d_in[16];
    float* out = (float*)d_out;

    fp16 *yf, *xf, *y1f, *woutf, *w1f, *w2f;
    float *z, *xln, *y2, *xT;
    cudaGetSymbolAddress((void**)&yf,  g_yf);
    cudaGetSymbolAddress((void**)&z,   g_z);
    cudaGetSymbolAddress((void**)&xln, g_xln);
    cudaGetSymbolAddress((void**)&xf,  g_xf);
    cudaGetSymbolAddress((void**)&y1f, g_y1f);
    cudaGetSymbolAddress((void**)&y2,  g_y2);
    cudaGetSymbolAddress((void**)&xT,  g_xT);
    cudaGetSymbolAddress((void**)&woutf, g_woutf);
    cudaGetSymbolAddress((void**)&w1f, g_w1f);
    cudaGetSymbolAddress((void**)&w2f, g_w2f);

    cudaFuncSetAttribute(gemm_mma, cudaFuncAttributeMaxDynamicSharedMemorySize, GEMM_SMEM);

    precompute_kernel<<<HDIM, NST>>>(log_dt, A_re, A_im, C_re, C_im);
    transpose_kernel<<<dim3(LSEQ / 32, HDIM / 32, BSZ), 256>>>(x, xT);

    scan_part1<<<(BSZ * HDIM * (SEG - 1)) / 16, 256>>>(xT);
    scan_combine<<<(BSZ * HDIM * NST) / 256, 256>>>();
    scan_part2<<<(BSZ * HDIM * SEG) / 16, 256>>>(xT, D_skip, yf);

    convert_w_kernel<<<(4 * HDIM * HDIM + 255) / 256, 256>>>(W_out, W1, W2);

    gemm_mma<<<dim3((2 * HDIM) / 128, ROWS / 128), 256, GEMM_SMEM>>>(
        yf, woutf, b_out, z, nullptr, HDIM, 2 * HDIM, 0);

    glu_ln_kernel<<<ROWS, 128>>>(z, x, g1, beta1, xln, xf);

    gemm_mma<<<dim3(HDIM / 128, ROWS / 128), 256, GEMM_SMEM>>>(
        xf, w1f, bc1, nullptr, y1f, HDIM, HDIM, 1);

    gemm_mma<<<dim3(HDIM / 128, ROWS / 128), 256, GEMM_SMEM>>>(
        y1f, w2f, bc2, y2, nullptr, HDIM, HDIM, 0);

    final_ln_kernel<<<ROWS, 128>>>(xln, y2, g2, beta2, out);
}